// round 4
// baseline (speedup 1.0000x reference)
#include <cuda_runtime.h>
#include <cuda_bf16.h>
#include <cstdint>

#define NN 200000
#define EE 3200000
#define BB 512
#define LL 1000

typedef unsigned long long ull;

// ------------------------ scratch (device globals, no allocs) ---------------
__device__ float g_dis[NN];
__device__ int   g_deg[NN];
__device__ float g_h[NN * 16];
__device__ float g_feat[NN * 16];
__device__ float g_agg[NN * 16];
__device__ float g_pool[BB * 16];
__device__ float g_t1[BB * 1024];
__device__ float g_xc[BB * 256];
__device__ float g_c1[BB * 32 * 331];
__device__ float g_c2[BB * 64 * 108];
__device__ float g_c3[BB * 128];
__device__ float g_f1[BB * 1024];
__device__ float g_f2[BB * 512];

// ------------------------ f32x2 helpers --------------------------------------
__device__ __forceinline__ ull pk2(float lo, float hi) {
    ull r; asm("mov.b64 %0, {%1, %2};" : "=l"(r) : "f"(lo), "f"(hi)); return r;
}
__device__ __forceinline__ float2 upk2(ull v) {
    float2 r; asm("mov.b64 {%0, %1}, %2;" : "=f"(r.x), "=f"(r.y) : "l"(v)); return r;
}
__device__ __forceinline__ void ffma2(ull& d, ull a, ull b) {
    asm("fma.rn.f32x2 %0, %1, %2, %0;" : "+l"(d) : "l"(a), "l"(b));
}

// ------------------------ graph branch --------------------------------------
__global__ void deg_kernel(const int* __restrict__ ei, int* __restrict__ deg) {
    int e = blockIdx.x * blockDim.x + threadIdx.x;
    if (e >= EE) return;
    atomicAdd(&deg[ei[EE + e]], 1);
}

__global__ void dis_kernel(const int* __restrict__ deg, float* __restrict__ dis) {
    int i = blockIdx.x * blockDim.x + threadIdx.x;
    if (i >= NN) return;
    dis[i] = rsqrtf((float)deg[i] + 1.0f);
}

// hs = dis[i] * (x @ W1)
__global__ void transform1(const float* __restrict__ x, const float* __restrict__ W,
                           const float* __restrict__ dis, float* __restrict__ hs) {
    __shared__ float Ws[16];
    int tid = threadIdx.x;
    if (tid < 16) Ws[tid] = W[tid];
    __syncthreads();
    int i = blockIdx.x * blockDim.x + tid;
    if (i >= NN) return;
    float xi[4];
#pragma unroll
    for (int f = 0; f < 4; f++) xi[f] = x[(size_t)i * 4 + f];
    float dd = dis[i];
#pragma unroll
    for (int fo = 0; fo < 4; fo++) {
        float s = 0.f;
#pragma unroll
        for (int fi = 0; fi < 4; fi++) s = fmaf(xi[fi], Ws[fi * 4 + fo], s);
        hs[(size_t)i * 4 + fo] = dd * s;
    }
}

// pure copy-scatter: agg[dst] += hs[src]
template <int F>
__global__ void scatter_kernel(const int* __restrict__ ei, const float* __restrict__ hs,
                               float* __restrict__ agg) {
    int e = blockIdx.x * blockDim.x + threadIdx.x;
    if (e >= EE) return;
    int s = __ldg(&ei[e]);
    int d = __ldg(&ei[EE + e]);
    const float4* p = reinterpret_cast<const float4*>(hs + (size_t)s * F);
    float* ad = agg + (size_t)d * F;
#pragma unroll
    for (int q = 0; q < F / 4; q++) {
        float4 m = p[q];
        asm volatile("red.global.add.v4.f32 [%0], {%1,%2,%3,%4};"
                     :: "l"(ad + q * 4), "f"(m.x), "f"(m.y), "f"(m.z), "f"(m.w)
                     : "memory");
    }
}

// feat = relu(dis*(agg+hs)+b); out = dis * (feat @ W)
template <int F, int FO>
__global__ void combine_transform(const float* __restrict__ agg, const float* __restrict__ hs,
                                  const float* __restrict__ dis, const float* __restrict__ bias,
                                  const float* __restrict__ W, float* __restrict__ out) {
    __shared__ float Ws[F * FO];
    __shared__ float bs[F];
    int tid = threadIdx.x;
    if (tid < F * FO) Ws[tid] = W[tid];
    if (tid < F) bs[tid] = bias[tid];
    __syncthreads();
    int i = blockIdx.x * blockDim.x + tid;
    if (i >= NN) return;
    float dd = dis[i];
    float v[F];
#pragma unroll
    for (int f = 0; f < F; f++)
        v[f] = fmaxf(dd * (agg[(size_t)i * F + f] + hs[(size_t)i * F + f]) + bs[f], 0.f);
#pragma unroll
    for (int fo = 0; fo < FO; fo++) {
        float s = 0.f;
#pragma unroll
        for (int f = 0; f < F; f++) s = fmaf(v[f], Ws[f * FO + fo], s);
        out[(size_t)i * FO + fo] = dd * s;
    }
}

// final GCN layer + batch max pool
__global__ void combine_pool(const float* __restrict__ agg, const float* __restrict__ hs,
                             const float* __restrict__ dis, const float* __restrict__ bias,
                             const int* __restrict__ batch, float* __restrict__ pool) {
    __shared__ float bs[16];
    int tid = threadIdx.x;
    if (tid < 16) bs[tid] = bias[tid];
    __syncthreads();
    int i = blockIdx.x * blockDim.x + tid;
    if (i >= NN) return;
    float dd = dis[i];
    float v[16];
#pragma unroll
    for (int f = 0; f < 16; f++)
        v[f] = fmaxf(dd * (agg[(size_t)i * 16 + f] + hs[(size_t)i * 16 + f]) + bs[f], 0.f);
    int bb = batch[i];
    unsigned m = __activemask();
    bool uni = false;
    if (m == 0xffffffffu) {
        int bb0 = __shfl_sync(0xffffffffu, bb, 0);
        uni = __all_sync(0xffffffffu, bb == bb0);
    }
    int* p = reinterpret_cast<int*>(pool + (size_t)bb * 16);
    if (uni) {
#pragma unroll
        for (int f = 0; f < 16; f++) {
            float t = v[f];
#pragma unroll
            for (int o = 16; o; o >>= 1) t = fmaxf(t, __shfl_xor_sync(0xffffffffu, t, o));
            v[f] = t;
        }
        if ((tid & 31) == 0)
#pragma unroll
            for (int f = 0; f < 16; f++) atomicMax(&p[f], __float_as_int(v[f]));
    } else {
#pragma unroll
        for (int f = 0; f < 16; f++) atomicMax(&p[f], __float_as_int(v[f]));
    }
}

// ------------------------ generic GEMM (f32x2) -------------------------------
__global__ void gemm_kernel(const float* __restrict__ A, const float* __restrict__ W,
                            const float* __restrict__ bias, float* __restrict__ C,
                            int M, int K, int Nc, int ldc, int coloff, int relu) {
    const int BM = 64, BN = 64, BK = 8;
    __shared__ __align__(16) float As[BK][BM];
    __shared__ __align__(16) float Bs[BK][BN];
    int tid = threadIdx.x;
    int tc = tid & 15, tr = tid >> 4;
    int brow = blockIdx.y * BM, bcol = blockIdx.x * BN;
    ull acc[4][2] = {};
    for (int k0 = 0; k0 < K; k0 += BK) {
        for (int i = tid; i < BM * BK; i += 256) {
            int kk = i & 7, m = i >> 3;
            int gr = brow + m, gc = k0 + kk;
            As[kk][m] = (gr < M && gc < K) ? A[(size_t)gr * K + gc] : 0.f;
        }
        for (int i = tid; i < BN * BK; i += 256) {
            int n = i & 63, kk = i >> 6;
            int gc = bcol + n, gr = k0 + kk;
            Bs[kk][n] = (gr < K && gc < Nc) ? W[(size_t)gr * Nc + gc] : 0.f;
        }
        __syncthreads();
#pragma unroll
        for (int kk = 0; kk < BK; kk++) {
            ull b0 = *reinterpret_cast<const ull*>(&Bs[kk][tc * 4]);
            ull b1 = *reinterpret_cast<const ull*>(&Bs[kk][tc * 4 + 2]);
            float4 av = *reinterpret_cast<const float4*>(&As[kk][tr * 4]);
            float aa[4] = {av.x, av.y, av.z, av.w};
#pragma unroll
            for (int u = 0; u < 4; u++) {
                ull a2 = pk2(aa[u], aa[u]);
                ffma2(acc[u][0], b0, a2);
                ffma2(acc[u][1], b1, a2);
            }
        }
        __syncthreads();
    }
#pragma unroll
    for (int u = 0; u < 4; u++) {
        int r = brow + tr * 4 + u;
        if (r >= M) continue;
#pragma unroll
        for (int v2 = 0; v2 < 2; v2++) {
            float2 pv = upk2(acc[u][v2]);
            float vals[2] = {pv.x, pv.y};
#pragma unroll
            for (int w = 0; w < 2; w++) {
                int c = bcol + tc * 4 + v2 * 2 + w;
                if (c >= Nc) continue;
                float val = vals[w] + bias[c];
                if (relu) val = fmaxf(val, 0.f);
                C[(size_t)r * ldc + coloff + c] = val;
            }
        }
    }
}

// ------------------------ conv inner: pre-packed pairs, zero-ALU x ----------
// xA: 16 floats = positions [p..p+15]; xB: 16 floats = positions [p+1..p+16].
// Both 16B-aligned. w: stride-32 float weights. 40 FFMA2, 8 LDS.128, 8 LDS.32.
__device__ __forceinline__ void ic_update2(const float* __restrict__ xA,
                                           const float* __restrict__ xB,
                                           const float* __restrict__ w, ull acc[5]) {
    ull e[8], o[8];
    const ulonglong2* pA = reinterpret_cast<const ulonglong2*>(xA);
    const ulonglong2* pB = reinterpret_cast<const ulonglong2*>(xB);
#pragma unroll
    for (int i = 0; i < 4; i++) {
        ulonglong2 va = pA[i]; e[2 * i] = va.x; e[2 * i + 1] = va.y;
        ulonglong2 vb = pB[i]; o[2 * i] = vb.x; o[2 * i + 1] = vb.y;
    }
#pragma unroll
    for (int k = 0; k < 8; k++) {
        float wv = w[k * 32];
        ull w2 = pk2(wv, wv);
        const ull* xpp = (k & 1) ? &o[k >> 1] : &e[k >> 1];
#pragma unroll
        for (int j = 0; j < 5; j++) ffma2(acc[j], xpp[j], w2);
    }
}

__device__ __forceinline__ void unpack9(const ull acc[5], float a[9]) {
#pragma unroll
    for (int j = 0; j < 4; j++) {
        float2 t = upk2(acc[j]);
        a[2 * j] = t.x; a[2 * j + 1] = t.y;
    }
    a[8] = upk2(acc[4]).x;
}

// conv1: target [B,L,5] -> conv(k=8)+relu+maxpool3 -> [B,32,331]
__global__ void conv1_kernel(const float* __restrict__ tgt, const float* __restrict__ K1,
                             const float* __restrict__ cb1, float* __restrict__ out) {
    __shared__ __align__(16) float inA[5 * 8 * 16];
    __shared__ __align__(16) float inB[5 * 8 * 16];
    __shared__ float w_s[5 * 8 * 32];
    __shared__ float b_s[32];
    int b = blockIdx.x;
    int g0 = blockIdx.y * 8;
    int tx = threadIdx.x, ty = threadIdx.y;
    int tid = ty * 32 + tx;
    int L0 = g0 * 9;
    for (int i = tid; i < 640; i += 256) {
        int c = i >> 7, t = (i >> 4) & 7, j = i & 15;
        int l = L0 + t * 9 + j;
        inA[i] = (l < LL) ? tgt[(size_t)b * (LL * 5) + l * 5 + c] : 0.f;
        inB[i] = (l + 1 < LL) ? tgt[(size_t)b * (LL * 5) + (l + 1) * 5 + c] : 0.f;
    }
    for (int i = tid; i < 1280; i += 256) {
        int oc = i / 40, r = i % 40;
        w_s[r * 32 + oc] = K1[i];
    }
    if (tid < 32) b_s[tid] = cb1[tid];
    __syncthreads();

    ull acc[5] = {};
#pragma unroll
    for (int ic = 0; ic < 5; ic++)
        ic_update2(&inA[(ic * 8 + ty) * 16], &inB[(ic * 8 + ty) * 16],
                   &w_s[ic * 256 + tx], acc);
    float a[9]; unpack9(acc, a);
    float bb = b_s[tx];
    int grp = g0 + ty;
#pragma unroll
    for (int p = 0; p < 3; p++) {
        int po = grp * 3 + p;
        if (po < 331) {
            float v = fmaxf(fmaxf(a[3 * p], a[3 * p + 1]), a[3 * p + 2]) + bb;
            out[((size_t)b * 32 + tx) * 331 + po] = fmaxf(v, 0.f);
        }
    }
}

// conv2: [B,32,331] -> conv(k=8)+relu+pool3 -> [B,64,108]
#define CONV2_SMEM ((4096 + 4096 + 8192 + 32) * 4)
__global__ void conv2_kernel(const float* __restrict__ c1, const float* __restrict__ K2,
                             const float* __restrict__ cb2, float* __restrict__ out) {
    extern __shared__ __align__(16) float sm2[];
    float* inA = sm2;            // 32*8*16
    float* inB = sm2 + 4096;     // 32*8*16
    float* w_s = sm2 + 8192;     // 32*8*32
    float* b_s = w_s + 8192;
    int b = blockIdx.x;
    int g0 = blockIdx.y * 8;
    int ocz = blockIdx.z;
    int tx = threadIdx.x, ty = threadIdx.y;
    int tid = ty * 32 + tx;
    int L0 = g0 * 9;
    for (int i = tid; i < 4096; i += 256) {
        int ic = i >> 7, t = (i >> 4) & 7, j = i & 15;
        int l = L0 + t * 9 + j;
        const float* row = c1 + ((size_t)b * 32 + ic) * 331;
        inA[i] = (l < 331) ? row[l] : 0.f;
        inB[i] = (l + 1 < 331) ? row[l + 1] : 0.f;
    }
    for (int i = tid; i < 8192; i += 256) {
        int oc = i / 256, r = i % 256;
        w_s[r * 32 + oc] = K2[((size_t)(ocz * 32 + oc)) * 256 + r];
    }
    if (tid < 32) b_s[tid] = cb2[ocz * 32 + tid];
    __syncthreads();

    int grp = g0 + ty;
    ull acc[5] = {};
#pragma unroll 2
    for (int ic = 0; ic < 32; ic++)
        ic_update2(&inA[(ic * 8 + ty) * 16], &inB[(ic * 8 + ty) * 16],
                   &w_s[ic * 256 + tx], acc);
    if (grp < 36) {
        float a[9]; unpack9(acc, a);
        float bb = b_s[tx];
        int oc = ocz * 32 + tx;
#pragma unroll
        for (int p = 0; p < 3; p++) {
            int po = grp * 3 + p;
            float v = fmaxf(fmaxf(a[3 * p], a[3 * p + 1]), a[3 * p + 2]) + bb;
            out[((size_t)b * 64 + oc) * 108 + po] = fmaxf(v, 0.f);
        }
    }
}

// conv3: [B,64,108] -> conv(k=8)+relu+pool3 -> mean over 33 -> [B,128]
#define CONV3_SMEM ((11264 + 11264 + 16384 + 32) * 4)
__global__ void conv3_kernel(const float* __restrict__ c2, const float* __restrict__ K3,
                             const float* __restrict__ cb3, float* __restrict__ c3) {
    extern __shared__ __align__(16) float sm3[];
    float* inA = sm3;              // 64*11*16
    float* inB = sm3 + 11264;
    float* w_s = sm3 + 22528;      // 64*8*32
    float* b_s = w_s + 16384;
    int b = blockIdx.x;
    int ocz = blockIdx.y;
    int tx = threadIdx.x, ty = threadIdx.y;
    int tid = ty * 32 + tx;        // 352 threads
    for (int i = tid; i < 11264; i += 352) {
        int ic = i / 176, r = i % 176, t = r / 16, j = r % 16;
        int l = t * 9 + j;
        const float* row = c2 + (size_t)b * 6912 + ic * 108;
        inA[i] = row[l];
        inB[i] = (l + 1 < 108) ? row[l + 1] : 0.f;
    }
    for (int i = tid; i < 16384; i += 352) {
        int oc = i / 512, r = i % 512;
        w_s[r * 32 + oc] = K3[((size_t)(ocz * 32 + oc)) * 512 + r];
    }
    if (tid < 32) b_s[tid] = cb3[ocz * 32 + tid];
    __syncthreads();

    ull acc[5] = {};
#pragma unroll 2
    for (int ic = 0; ic < 64; ic++)
        ic_update2(&inA[(ic * 11 + ty) * 16], &inB[(ic * 11 + ty) * 16],
                   &w_s[ic * 256 + tx], acc);
    float a[9]; unpack9(acc, a);
    float bb = b_s[tx];
    float s = 0.f;
#pragma unroll
    for (int p = 0; p < 3; p++) {
        float v = fmaxf(fmaxf(a[3 * p], a[3 * p + 1]), a[3 * p + 2]) + bb;
        s += fmaxf(v, 0.f);
    }
    atomicAdd(&c3[(size_t)b * 128 + ocz * 32 + tx], s * (1.0f / 33.0f));
}

// ------------------------ stream fork/join context --------------------------
struct Ctx {
    cudaStream_t s2 = nullptr;
    cudaEvent_t eF = nullptr, eJ = nullptr;
    bool ok = false;
    Ctx() {
        ok = (cudaStreamCreateWithFlags(&s2, cudaStreamNonBlocking) == cudaSuccess) &&
             (cudaEventCreateWithFlags(&eF, cudaEventDisableTiming) == cudaSuccess) &&
             (cudaEventCreateWithFlags(&eJ, cudaEventDisableTiming) == cudaSuccess);
    }
};
static Ctx g_ctx;

// ------------------------ host orchestration --------------------------------
extern "C" void kernel_launch(void* const* d_in, const int* in_sizes, int n_in,
                              void* d_out, int out_size) {
    const float* x    = (const float*)d_in[0];
    const int*   ei   = (const int*)d_in[1];
    const int*   batch= (const int*)d_in[2];
    const float* tgt  = (const float*)d_in[3];
    const float* W1 = (const float*)d_in[4];   const float* b1 = (const float*)d_in[5];
    const float* W2 = (const float*)d_in[6];   const float* b2 = (const float*)d_in[7];
    const float* W3 = (const float*)d_in[8];   const float* b3 = (const float*)d_in[9];
    const float* Wg1= (const float*)d_in[10];  const float* bg1= (const float*)d_in[11];
    const float* Wg2= (const float*)d_in[12];  const float* bg2= (const float*)d_in[13];
    const float* K1 = (const float*)d_in[14];  const float* cb1= (const float*)d_in[15];
    const float* K2 = (const float*)d_in[16];  const float* cb2= (const float*)d_in[17];
    const float* K3 = (const float*)d_in[18];  const float* cb3= (const float*)d_in[19];
    const float* Wxt= (const float*)d_in[20];  const float* bxt= (const float*)d_in[21];
    const float* Wf1= (const float*)d_in[22];  const float* bf1= (const float*)d_in[23];
    const float* Wf2= (const float*)d_in[24];  const float* bf2= (const float*)d_in[25];
    const float* Wo = (const float*)d_in[26];  const float* bo = (const float*)d_in[27];
    float* out = (float*)d_out;

    float *p_dis, *p_h, *p_feat, *p_agg, *p_pool, *p_t1, *p_xc, *p_c1, *p_c2, *p_c3, *p_f1, *p_f2;
    int* p_deg;
    cudaGetSymbolAddress((void**)&p_dis, g_dis);
    cudaGetSymbolAddress((void**)&p_deg, g_deg);
    cudaGetSymbolAddress((void**)&p_h, g_h);
    cudaGetSymbolAddress((void**)&p_feat, g_feat);
    cudaGetSymbolAddress((void**)&p_agg, g_agg);
    cudaGetSymbolAddress((void**)&p_pool, g_pool);
    cudaGetSymbolAddress((void**)&p_t1, g_t1);
    cudaGetSymbolAddress((void**)&p_xc, g_xc);
    cudaGetSymbolAddress((void**)&p_c1, g_c1);
    cudaGetSymbolAddress((void**)&p_c2, g_c2);
    cudaGetSymbolAddress((void**)&p_c3, g_c3);
    cudaGetSymbolAddress((void**)&p_f1, g_f1);
    cudaGetSymbolAddress((void**)&p_f2, g_f2);

    const int TPB = 256;
    const int gE = (EE + TPB - 1) / TPB;
    const int gN = (NN + TPB - 1) / TPB;

    bool fork = g_ctx.ok;
    cudaStream_t sg = fork ? g_ctx.s2 : (cudaStream_t)0;

    if (fork) {
        cudaEventRecord(g_ctx.eF, 0);
        cudaStreamWaitEvent(sg, g_ctx.eF, 0);
    }

    cudaFuncSetAttribute(conv2_kernel, cudaFuncAttributeMaxDynamicSharedMemorySize, CONV2_SMEM);
    cudaFuncSetAttribute(conv3_kernel, cudaFuncAttributeMaxDynamicSharedMemorySize, CONV3_SMEM);

    // Launch order: ncu -s 5 -c 1 profiles the 6th launch = conv2.
    cudaMemsetAsync(p_deg, 0, NN * sizeof(int), sg);               // 1
    deg_kernel<<<gE, TPB, 0, sg>>>(ei, p_deg);                     // 2
    dis_kernel<<<gN, TPB, 0, sg>>>(p_deg, p_dis);                  // 3
    transform1<<<gN, TPB, 0, sg>>>(x, W1, p_dis, p_h);             // 4
    conv1_kernel<<<dim3(BB, 14), dim3(32, 8)>>>(tgt, K1, cb1, p_c1);                   // 5
    conv2_kernel<<<dim3(BB, 5, 2), dim3(32, 8), CONV2_SMEM>>>(p_c1, K2, cb2, p_c2);    // 6 <- profiled

    // ---- rest of graph branch (stream sg) ----
    cudaMemsetAsync(p_agg, 0, (size_t)NN * 4 * sizeof(float), sg);
    scatter_kernel<4><<<gE, TPB, 0, sg>>>(ei, p_h, p_agg);
    combine_transform<4, 8><<<gN, TPB, 0, sg>>>(p_agg, p_h, p_dis, b1, W2, p_feat);

    cudaMemsetAsync(p_agg, 0, (size_t)NN * 8 * sizeof(float), sg);
    scatter_kernel<8><<<gE, TPB, 0, sg>>>(ei, p_feat, p_agg);
    combine_transform<8, 16><<<gN, TPB, 0, sg>>>(p_agg, p_feat, p_dis, b2, W3, p_h);

    cudaMemsetAsync(p_agg, 0, (size_t)NN * 16 * sizeof(float), sg);
    scatter_kernel<16><<<gE, TPB, 0, sg>>>(ei, p_h, p_agg);
    cudaMemsetAsync(p_pool, 0, BB * 16 * sizeof(float), sg);
    combine_pool<<<gN, TPB, 0, sg>>>(p_agg, p_h, p_dis, b3, batch, p_pool);

    gemm_kernel<<<dim3(16, 8), 256, 0, sg>>>(p_pool, Wg1, bg1, p_t1, BB, 16, 1024, 1024, 0, 1);
    gemm_kernel<<<dim3(2, 8), 256, 0, sg>>>(p_t1, Wg2, bg2, p_xc, BB, 1024, 128, 256, 0, 0);
    if (fork) cudaEventRecord(g_ctx.eJ, sg);

    // ---- rest of conv branch (stream 0) ----
    cudaMemsetAsync(p_c3, 0, BB * 128 * sizeof(float));
    conv3_kernel<<<dim3(BB, 4), dim3(32, 11), CONV3_SMEM>>>(p_c2, K3, cb3, p_c3);
    gemm_kernel<<<dim3(2, 8), 256>>>(p_c3, Wxt, bxt, p_xc, BB, 128, 128, 256, 128, 1);

    // ---- join + fusion head (stream 0) ----
    if (fork) cudaStreamWaitEvent(0, g_ctx.eJ, 0);
    gemm_kernel<<<dim3(16, 8), 256>>>(p_xc, Wf1, bf1, p_f1, BB, 256, 1024, 1024, 0, 1);
    gemm_kernel<<<dim3(8, 8), 256>>>(p_f1, Wf2, bf2, p_f2, BB, 1024, 512, 512, 0, 1);
    gemm_kernel<<<dim3(1, 8), 256>>>(p_f2, Wo, bo, out, BB, 512, 2, 2, 0, 0);
}

// round 6
// speedup vs baseline: 1.1644x; 1.1644x over previous
#include <cuda_runtime.h>
#include <cuda_bf16.h>
#include <cstdint>

#define NN 200000
#define EE 3200000
#define BB 512
#define LL 1000

typedef unsigned long long ull;

// ------------------------ scratch (device globals, no allocs) ---------------
__device__ float g_dis[NN];
__device__ int   g_deg[NN];
__device__ float g_h[NN * 16];
__device__ float g_feat[NN * 16];
__device__ float g_agg[NN * 16];
__device__ float g_pool[BB * 16];
__device__ float g_t1[BB * 1024];
__device__ float g_xc[BB * 256];
__device__ float g_c1[BB * 32 * 331];
__device__ float g_c2[BB * 64 * 108];
__device__ float g_c3[BB * 128];
__device__ float g_f1[BB * 1024];
__device__ float g_f2[BB * 512];

// ------------------------ f32x2 helpers --------------------------------------
__device__ __forceinline__ ull pk2(float lo, float hi) {
    ull r; asm("mov.b64 %0, {%1, %2};" : "=l"(r) : "f"(lo), "f"(hi)); return r;
}
__device__ __forceinline__ float2 upk2(ull v) {
    float2 r; asm("mov.b64 {%0, %1}, %2;" : "=f"(r.x), "=f"(r.y) : "l"(v)); return r;
}
__device__ __forceinline__ void ffma2(ull& d, ull a, ull b) {
    asm("fma.rn.f32x2 %0, %1, %2, %0;" : "+l"(d) : "l"(a), "l"(b));
}

// ------------------------ graph branch --------------------------------------
__global__ void deg_kernel(const int* __restrict__ ei, int* __restrict__ deg) {
    int e = blockIdx.x * blockDim.x + threadIdx.x;
    if (e >= EE) return;
    atomicAdd(&deg[ei[EE + e]], 1);
}

__global__ void dis_kernel(const int* __restrict__ deg, float* __restrict__ dis) {
    int i = blockIdx.x * blockDim.x + threadIdx.x;
    if (i >= NN) return;
    dis[i] = rsqrtf((float)deg[i] + 1.0f);
}

// hs = dis[i] * (x @ W1)
__global__ void transform1(const float* __restrict__ x, const float* __restrict__ W,
                           const float* __restrict__ dis, float* __restrict__ hs) {
    __shared__ float Ws[16];
    int tid = threadIdx.x;
    if (tid < 16) Ws[tid] = W[tid];
    __syncthreads();
    int i = blockIdx.x * blockDim.x + tid;
    if (i >= NN) return;
    float xi[4];
#pragma unroll
    for (int f = 0; f < 4; f++) xi[f] = x[(size_t)i * 4 + f];
    float dd = dis[i];
#pragma unroll
    for (int fo = 0; fo < 4; fo++) {
        float s = 0.f;
#pragma unroll
        for (int fi = 0; fi < 4; fi++) s = fmaf(xi[fi], Ws[fi * 4 + fo], s);
        hs[(size_t)i * 4 + fo] = dd * s;
    }
}

// pure copy-scatter: agg[dst] += hs[src]
template <int F>
__global__ void scatter_kernel(const int* __restrict__ ei, const float* __restrict__ hs,
                               float* __restrict__ agg) {
    int e = blockIdx.x * blockDim.x + threadIdx.x;
    if (e >= EE) return;
    int s = __ldg(&ei[e]);
    int d = __ldg(&ei[EE + e]);
    const float4* p = reinterpret_cast<const float4*>(hs + (size_t)s * F);
    float* ad = agg + (size_t)d * F;
#pragma unroll
    for (int q = 0; q < F / 4; q++) {
        float4 m = p[q];
        asm volatile("red.global.add.v4.f32 [%0], {%1,%2,%3,%4};"
                     :: "l"(ad + q * 4), "f"(m.x), "f"(m.y), "f"(m.z), "f"(m.w)
                     : "memory");
    }
}

// feat = relu(dis*(agg+hs)+b); out = dis * (feat @ W)
template <int F, int FO>
__global__ void combine_transform(const float* __restrict__ agg, const float* __restrict__ hs,
                                  const float* __restrict__ dis, const float* __restrict__ bias,
                                  const float* __restrict__ W, float* __restrict__ out) {
    __shared__ float Ws[F * FO];
    __shared__ float bs[F];
    int tid = threadIdx.x;
    if (tid < F * FO) Ws[tid] = W[tid];
    if (tid < F) bs[tid] = bias[tid];
    __syncthreads();
    int i = blockIdx.x * blockDim.x + tid;
    if (i >= NN) return;
    float dd = dis[i];
    float v[F];
#pragma unroll
    for (int f = 0; f < F; f++)
        v[f] = fmaxf(dd * (agg[(size_t)i * F + f] + hs[(size_t)i * F + f]) + bs[f], 0.f);
#pragma unroll
    for (int fo = 0; fo < FO; fo++) {
        float s = 0.f;
#pragma unroll
        for (int f = 0; f < F; f++) s = fmaf(v[f], Ws[f * FO + fo], s);
        out[(size_t)i * FO + fo] = dd * s;
    }
}

// final GCN layer + batch max pool
__global__ void combine_pool(const float* __restrict__ agg, const float* __restrict__ hs,
                             const float* __restrict__ dis, const float* __restrict__ bias,
                             const int* __restrict__ batch, float* __restrict__ pool) {
    __shared__ float bs[16];
    int tid = threadIdx.x;
    if (tid < 16) bs[tid] = bias[tid];
    __syncthreads();
    int i = blockIdx.x * blockDim.x + tid;
    if (i >= NN) return;
    float dd = dis[i];
    float v[16];
#pragma unroll
    for (int f = 0; f < 16; f++)
        v[f] = fmaxf(dd * (agg[(size_t)i * 16 + f] + hs[(size_t)i * 16 + f]) + bs[f], 0.f);
    int bb = batch[i];
    unsigned m = __activemask();
    bool uni = false;
    if (m == 0xffffffffu) {
        int bb0 = __shfl_sync(0xffffffffu, bb, 0);
        uni = __all_sync(0xffffffffu, bb == bb0);
    }
    int* p = reinterpret_cast<int*>(pool + (size_t)bb * 16);
    if (uni) {
#pragma unroll
        for (int f = 0; f < 16; f++) {
            float t = v[f];
#pragma unroll
            for (int o = 16; o; o >>= 1) t = fmaxf(t, __shfl_xor_sync(0xffffffffu, t, o));
            v[f] = t;
        }
        if ((tid & 31) == 0)
#pragma unroll
            for (int f = 0; f < 16; f++) atomicMax(&p[f], __float_as_int(v[f]));
    } else {
#pragma unroll
        for (int f = 0; f < 16; f++) atomicMax(&p[f], __float_as_int(v[f]));
    }
}

// ------------------------ generic GEMM (f32x2) -------------------------------
__global__ void gemm_kernel(const float* __restrict__ A, const float* __restrict__ W,
                            const float* __restrict__ bias, float* __restrict__ C,
                            int M, int K, int Nc, int ldc, int coloff, int relu) {
    const int BM = 64, BN = 64, BK = 8;
    __shared__ __align__(16) float As[BK][BM];
    __shared__ __align__(16) float Bs[BK][BN];
    int tid = threadIdx.x;
    int tc = tid & 15, tr = tid >> 4;
    int brow = blockIdx.y * BM, bcol = blockIdx.x * BN;
    ull acc[4][2] = {};
    for (int k0 = 0; k0 < K; k0 += BK) {
        for (int i = tid; i < BM * BK; i += 256) {
            int kk = i & 7, m = i >> 3;
            int gr = brow + m, gc = k0 + kk;
            As[kk][m] = (gr < M && gc < K) ? A[(size_t)gr * K + gc] : 0.f;
        }
        for (int i = tid; i < BN * BK; i += 256) {
            int n = i & 63, kk = i >> 6;
            int gc = bcol + n, gr = k0 + kk;
            Bs[kk][n] = (gr < K && gc < Nc) ? W[(size_t)gr * Nc + gc] : 0.f;
        }
        __syncthreads();
#pragma unroll
        for (int kk = 0; kk < BK; kk++) {
            ull b0 = *reinterpret_cast<const ull*>(&Bs[kk][tc * 4]);
            ull b1 = *reinterpret_cast<const ull*>(&Bs[kk][tc * 4 + 2]);
            float4 av = *reinterpret_cast<const float4*>(&As[kk][tr * 4]);
            float aa[4] = {av.x, av.y, av.z, av.w};
#pragma unroll
            for (int u = 0; u < 4; u++) {
                ull a2 = pk2(aa[u], aa[u]);
                ffma2(acc[u][0], b0, a2);
                ffma2(acc[u][1], b1, a2);
            }
        }
        __syncthreads();
    }
#pragma unroll
    for (int u = 0; u < 4; u++) {
        int r = brow + tr * 4 + u;
        if (r >= M) continue;
#pragma unroll
        for (int v2 = 0; v2 < 2; v2++) {
            float2 pv = upk2(acc[u][v2]);
            float vals[2] = {pv.x, pv.y};
#pragma unroll
            for (int w = 0; w < 2; w++) {
                int c = bcol + tc * 4 + v2 * 2 + w;
                if (c >= Nc) continue;
                float val = vals[w] + bias[c];
                if (relu) val = fmaxf(val, 0.f);
                C[(size_t)r * ldc + coloff + c] = val;
            }
        }
    }
}

// ------------------------ conv inner helpers --------------------------------
// Load 16 even pairs + 16 odd pairs (xB = xA shifted by one position).
__device__ __forceinline__ void load_eo(const float* __restrict__ xA,
                                        const float* __restrict__ xB, ull e[8], ull o[8]) {
    const ulonglong2* pA = reinterpret_cast<const ulonglong2*>(xA);
    const ulonglong2* pB = reinterpret_cast<const ulonglong2*>(xB);
#pragma unroll
    for (int i = 0; i < 4; i++) {
        ulonglong2 va = pA[i]; e[2 * i] = va.x; e[2 * i + 1] = va.y;
        ulonglong2 vb = pB[i]; o[2 * i] = vb.x; o[2 * i + 1] = vb.y;
    }
}

// 1 output channel, weight smem stride 33 (conflict-free padded)
__device__ __forceinline__ void ic_upd_1oc(const float* __restrict__ xA,
                                           const float* __restrict__ xB,
                                           const float* __restrict__ w, ull a0[5]) {
    ull e[8], o[8];
    load_eo(xA, xB, e, o);
#pragma unroll
    for (int k = 0; k < 8; k++) {
        float wv = w[k * 33];
        ull w2 = pk2(wv, wv);
        const ull* xpp = (k & 1) ? &o[k >> 1] : &e[k >> 1];
#pragma unroll
        for (int j = 0; j < 5; j++) ffma2(a0[j], xpp[j], w2);
    }
}

// 2 output channels (oc, oc+32), weight smem stride 65
__device__ __forceinline__ void ic_upd_2oc(const float* __restrict__ xA,
                                           const float* __restrict__ xB,
                                           const float* __restrict__ w,
                                           ull a0[5], ull a1[5]) {
    ull e[8], o[8];
    load_eo(xA, xB, e, o);
#pragma unroll
    for (int k = 0; k < 8; k++) {
        float w0 = w[k * 65];
        float w1 = w[k * 65 + 32];
        ull w20 = pk2(w0, w0);
        ull w21 = pk2(w1, w1);
        const ull* xpp = (k & 1) ? &o[k >> 1] : &e[k >> 1];
#pragma unroll
        for (int j = 0; j < 5; j++) {
            ffma2(a0[j], xpp[j], w20);
            ffma2(a1[j], xpp[j], w21);
        }
    }
}

__device__ __forceinline__ void unpack9(const ull acc[5], float a[9]) {
#pragma unroll
    for (int j = 0; j < 4; j++) {
        float2 t = upk2(acc[j]);
        a[2 * j] = t.x; a[2 * j + 1] = t.y;
    }
    a[8] = upk2(acc[4]).x;
}

// conv1: target [B,L,5] -> conv(k=8)+relu+maxpool3 -> [B,32,331]
__global__ void conv1_kernel(const float* __restrict__ tgt, const float* __restrict__ K1,
                             const float* __restrict__ cb1, float* __restrict__ out) {
    __shared__ __align__(16) float inA[5 * 8 * 16];
    __shared__ __align__(16) float inB[5 * 8 * 16];
    __shared__ float w_s[40 * 33];   // [(ic*8+k)*33 + oc]
    __shared__ float b_s[32];
    int b = blockIdx.x;
    int g0 = blockIdx.y * 8;
    int tx = threadIdx.x, ty = threadIdx.y;
    int tid = ty * 32 + tx;
    int L0 = g0 * 9;
    for (int i = tid; i < 640; i += 256) {
        int c = i >> 7, t = (i >> 4) & 7, j = i & 15;
        int l = L0 + t * 9 + j;
        inA[i] = (l < LL) ? tgt[(size_t)b * (LL * 5) + l * 5 + c] : 0.f;
        inB[i] = (l + 1 < LL) ? tgt[(size_t)b * (LL * 5) + (l + 1) * 5 + c] : 0.f;
    }
    // FIXED: cover all 32 oc x 40 r pairs (2048-slot loop, r<40 guard).
    for (int i = tid; i < 2048; i += 256) {
        int oc = i >> 6, r = i & 63;
        if (r < 40) w_s[r * 33 + oc] = K1[oc * 40 + r];
    }
    if (tid < 32) b_s[tid] = cb1[tid];
    __syncthreads();

    ull acc[5] = {};
#pragma unroll
    for (int ic = 0; ic < 5; ic++)
        ic_upd_1oc(&inA[(ic * 8 + ty) * 16], &inB[(ic * 8 + ty) * 16],
                   &w_s[ic * 8 * 33 + tx], acc);
    float a[9]; unpack9(acc, a);
    float bb = b_s[tx];
    int grp = g0 + ty;
#pragma unroll
    for (int p = 0; p < 3; p++) {
        int po = grp * 3 + p;
        if (po < 331) {
            float v = fmaxf(fmaxf(a[3 * p], a[3 * p + 1]), a[3 * p + 2]) + bb;
            out[((size_t)b * 32 + tx) * 331 + po] = fmaxf(v, 0.f);
        }
    }
}

// conv2: [B,32,331] -> conv(k=8)+relu+pool3 -> [B,64,108]; 64 oc, 2 per thread
#define CONV2_SMEM ((4096 + 4096 + 256 * 65 + 64) * 4)
__global__ void conv2_kernel(const float* __restrict__ c1, const float* __restrict__ K2,
                             const float* __restrict__ cb2, float* __restrict__ out) {
    extern __shared__ __align__(16) float sm2[];
    float* inA = sm2;                 // 32*8*16
    float* inB = sm2 + 4096;
    float* w_s = sm2 + 8192;          // [(ic*8+k)*65 + oc], oc<64
    float* b_s = w_s + 256 * 65;
    int b = blockIdx.x;
    int g0 = blockIdx.y * 8;
    int tx = threadIdx.x, ty = threadIdx.y;
    int tid = ty * 32 + tx;
    int L0 = g0 * 9;
    for (int i = tid; i < 4096; i += 256) {
        int ic = i >> 7, t = (i >> 4) & 7, j = i & 15;
        int l = L0 + t * 9 + j;
        const float* row = c1 + ((size_t)b * 32 + ic) * 331;
        inA[i] = (l < 331) ? row[l] : 0.f;
        inB[i] = (l + 1 < 331) ? row[l + 1] : 0.f;
    }
    // K2[oc][r], r = ic*8+k (256). Coalesced LDG (consecutive r), conflict-free STS.
    for (int i = tid; i < 64 * 256; i += 256) {
        int r = i & 255, oc = i >> 8;
        w_s[r * 65 + oc] = K2[(size_t)oc * 256 + r];
    }
    if (tid < 64) b_s[tid] = cb2[tid];
    __syncthreads();

    int grp = g0 + ty;
    ull a0[5] = {}, a1[5] = {};
    for (int ic = 0; ic < 32; ic++)
        ic_upd_2oc(&inA[(ic * 8 + ty) * 16], &inB[(ic * 8 + ty) * 16],
                   &w_s[ic * 8 * 65 + tx], a0, a1);
    if (grp < 36) {
        float v0[9], v1[9]; unpack9(a0, v0); unpack9(a1, v1);
        float bb0 = b_s[tx], bb1 = b_s[tx + 32];
        float* o0 = out + ((size_t)b * 64 + tx) * 108;
        float* o1 = out + ((size_t)b * 64 + tx + 32) * 108;
#pragma unroll
        for (int p = 0; p < 3; p++) {
            int po = grp * 3 + p;
            o0[po] = fmaxf(fmaxf(fmaxf(v0[3 * p], v0[3 * p + 1]), v0[3 * p + 2]) + bb0, 0.f);
            o1[po] = fmaxf(fmaxf(fmaxf(v1[3 * p], v1[3 * p + 1]), v1[3 * p + 2]) + bb1, 0.f);
        }
    }
}

// conv3: [B,64,108] -> conv+relu+pool3 -> mean33 -> [B,128]; 64 oc/block, 2/thread
#define CONV3_SMEM ((11264 + 11264 + 512 * 65 + 64) * 4)
__global__ void conv3_kernel(const float* __restrict__ c2, const float* __restrict__ K3,
                             const float* __restrict__ cb3, float* __restrict__ c3) {
    extern __shared__ __align__(16) float sm3[];
    float* inA = sm3;                  // 64*11*16
    float* inB = sm3 + 11264;
    float* w_s = sm3 + 22528;          // [(ic*8+k)*65 + oc], oc<64
    float* b_s = w_s + 512 * 65;
    int b = blockIdx.x;
    int ocz = blockIdx.y;              // 0,1 -> oc base 0,64
    int tx = threadIdx.x, ty = threadIdx.y;
    int tid = ty * 32 + tx;            // 352 threads
    for (int i = tid; i < 11264; i += 352) {
        int ic = i / 176, r = i % 176, t = r / 16, j = r % 16;
        int l = t * 9 + j;
        const float* row = c2 + (size_t)b * 6912 + ic * 108;
        inA[i] = row[l];
        inB[i] = (l + 1 < 108) ? row[l + 1] : 0.f;
    }
    for (int i = tid; i < 64 * 512; i += 352) {
        int r = i & 511, oc = i >> 9;
        w_s[r * 65 + oc] = K3[((size_t)(ocz * 64 + oc)) * 512 + r];
    }
    if (tid < 64) b_s[tid] = cb3[ocz * 64 + tid];
    __syncthreads();

    ull a0[5] = {}, a1[5] = {};
    for (int ic = 0; ic < 64; ic++)
        ic_upd_2oc(&inA[(ic * 11 + ty) * 16], &inB[(ic * 11 + ty) * 16],
                   &w_s[ic * 8 * 65 + tx], a0, a1);
    float v0[9], v1[9]; unpack9(a0, v0); unpack9(a1, v1);
    float bb0 = b_s[tx], bb1 = b_s[tx + 32];
    float s0 = 0.f, s1 = 0.f;
#pragma unroll
    for (int p = 0; p < 3; p++) {
        s0 += fmaxf(fmaxf(fmaxf(v0[3 * p], v0[3 * p + 1]), v0[3 * p + 2]) + bb0, 0.f);
        s1 += fmaxf(fmaxf(fmaxf(v1[3 * p], v1[3 * p + 1]), v1[3 * p + 2]) + bb1, 0.f);
    }
    atomicAdd(&c3[(size_t)b * 128 + ocz * 64 + tx], s0 * (1.0f / 33.0f));
    atomicAdd(&c3[(size_t)b * 128 + ocz * 64 + tx + 32], s1 * (1.0f / 33.0f));
}

// ------------------------ stream fork/join context --------------------------
struct Ctx {
    cudaStream_t s2 = nullptr;
    cudaEvent_t eF = nullptr, eJ = nullptr;
    bool ok = false;
    Ctx() {
        ok = (cudaStreamCreateWithFlags(&s2, cudaStreamNonBlocking) == cudaSuccess) &&
             (cudaEventCreateWithFlags(&eF, cudaEventDisableTiming) == cudaSuccess) &&
             (cudaEventCreateWithFlags(&eJ, cudaEventDisableTiming) == cudaSuccess);
    }
};
static Ctx g_ctx;

// ------------------------ host orchestration --------------------------------
extern "C" void kernel_launch(void* const* d_in, const int* in_sizes, int n_in,
                              void* d_out, int out_size) {
    const float* x    = (const float*)d_in[0];
    const int*   ei   = (const int*)d_in[1];
    const int*   batch= (const int*)d_in[2];
    const float* tgt  = (const float*)d_in[3];
    const float* W1 = (const float*)d_in[4];   const float* b1 = (const float*)d_in[5];
    const float* W2 = (const float*)d_in[6];   const float* b2 = (const float*)d_in[7];
    const float* W3 = (const float*)d_in[8];   const float* b3 = (const float*)d_in[9];
    const float* Wg1= (const float*)d_in[10];  const float* bg1= (const float*)d_in[11];
    const float* Wg2= (const float*)d_in[12];  const float* bg2= (const float*)d_in[13];
    const float* K1 = (const float*)d_in[14];  const float* cb1= (const float*)d_in[15];
    const float* K2 = (const float*)d_in[16];  const float* cb2= (const float*)d_in[17];
    const float* K3 = (const float*)d_in[18];  const float* cb3= (const float*)d_in[19];
    const float* Wxt= (const float*)d_in[20];  const float* bxt= (const float*)d_in[21];
    const float* Wf1= (const float*)d_in[22];  const float* bf1= (const float*)d_in[23];
    const float* Wf2= (const float*)d_in[24];  const float* bf2= (const float*)d_in[25];
    const float* Wo = (const float*)d_in[26];  const float* bo = (const float*)d_in[27];
    float* out = (float*)d_out;

    float *p_dis, *p_h, *p_feat, *p_agg, *p_pool, *p_t1, *p_xc, *p_c1, *p_c2, *p_c3, *p_f1, *p_f2;
    int* p_deg;
    cudaGetSymbolAddress((void**)&p_dis, g_dis);
    cudaGetSymbolAddress((void**)&p_deg, g_deg);
    cudaGetSymbolAddress((void**)&p_h, g_h);
    cudaGetSymbolAddress((void**)&p_feat, g_feat);
    cudaGetSymbolAddress((void**)&p_agg, g_agg);
    cudaGetSymbolAddress((void**)&p_pool, g_pool);
    cudaGetSymbolAddress((void**)&p_t1, g_t1);
    cudaGetSymbolAddress((void**)&p_xc, g_xc);
    cudaGetSymbolAddress((void**)&p_c1, g_c1);
    cudaGetSymbolAddress((void**)&p_c2, g_c2);
    cudaGetSymbolAddress((void**)&p_c3, g_c3);
    cudaGetSymbolAddress((void**)&p_f1, g_f1);
    cudaGetSymbolAddress((void**)&p_f2, g_f2);

    const int TPB = 256;
    const int gE = (EE + TPB - 1) / TPB;
    const int gN = (NN + TPB - 1) / TPB;

    bool fork = g_ctx.ok;
    cudaStream_t sg = fork ? g_ctx.s2 : (cudaStream_t)0;

    if (fork) {
        cudaEventRecord(g_ctx.eF, 0);
        cudaStreamWaitEvent(sg, g_ctx.eF, 0);
    }

    cudaFuncSetAttribute(conv2_kernel, cudaFuncAttributeMaxDynamicSharedMemorySize, CONV2_SMEM);
    cudaFuncSetAttribute(conv3_kernel, cudaFuncAttributeMaxDynamicSharedMemorySize, CONV3_SMEM);

    // Submission order puts conv2/conv3 in the ncu window (-s 5 -c 1).
    cudaMemsetAsync(p_deg, 0, NN * sizeof(int), sg);                                 // 1
    deg_kernel<<<gE, TPB, 0, sg>>>(ei, p_deg);                                       // 2
    conv1_kernel<<<dim3(BB, 14), dim3(32, 8)>>>(tgt, K1, cb1, p_c1);                 // 3
    cudaMemsetAsync(p_c3, 0, BB * 128 * sizeof(float));                              // 4
    conv2_kernel<<<dim3(BB, 5), dim3(32, 8), CONV2_SMEM>>>(p_c1, K2, cb2, p_c2);     // 5
    conv3_kernel<<<dim3(BB, 2), dim3(32, 11), CONV3_SMEM>>>(p_c2, K3, cb3, p_c3);    // 6
    gemm_kernel<<<dim3(2, 8), 256>>>(p_c3, Wxt, bxt, p_xc, BB, 128, 128, 256, 128, 1);

    // ---- graph branch (stream sg) ----
    dis_kernel<<<gN, TPB, 0, sg>>>(p_deg, p_dis);
    transform1<<<gN, TPB, 0, sg>>>(x, W1, p_dis, p_h);
    cudaMemsetAsync(p_agg, 0, (size_t)NN * 4 * sizeof(float), sg);
    scatter_kernel<4><<<gE, TPB, 0, sg>>>(ei, p_h, p_agg);
    combine_transform<4, 8><<<gN, TPB, 0, sg>>>(p_agg, p_h, p_dis, b1, W2, p_feat);

    cudaMemsetAsync(p_agg, 0, (size_t)NN * 8 * sizeof(float), sg);
    scatter_kernel<8><<<gE, TPB, 0, sg>>>(ei, p_feat, p_agg);
    combine_transform<8, 16><<<gN, TPB, 0, sg>>>(p_agg, p_feat, p_dis, b2, W3, p_h);

    cudaMemsetAsync(p_agg, 0, (size_t)NN * 16 * sizeof(float), sg);
    scatter_kernel<16><<<gE, TPB, 0, sg>>>(ei, p_h, p_agg);
    cudaMemsetAsync(p_pool, 0, BB * 16 * sizeof(float), sg);
    combine_pool<<<gN, TPB, 0, sg>>>(p_agg, p_h, p_dis, b3, batch, p_pool);

    gemm_kernel<<<dim3(16, 8), 256, 0, sg>>>(p_pool, Wg1, bg1, p_t1, BB, 16, 1024, 1024, 0, 1);
    gemm_kernel<<<dim3(2, 8), 256, 0, sg>>>(p_t1, Wg2, bg2, p_xc, BB, 1024, 128, 256, 0, 0);
    if (fork) cudaEventRecord(g_ctx.eJ, sg);

    // ---- join + fusion head (stream 0) ----
    if (fork) cudaStreamWaitEvent(0, g_ctx.eJ, 0);
    gemm_kernel<<<dim3(16, 8), 256>>>(p_xc, Wf1, bf1, p_f1, BB, 256, 1024, 1024, 0, 1);
    gemm_kernel<<<dim3(8, 8), 256>>>(p_f1, Wf2, bf2, p_f2, BB, 1024, 512, 512, 0, 1);
    gemm_kernel<<<dim3(1, 8), 256>>>(p_f2, Wo, bo, out, BB, 512, 2, 2, 0, 0);
}

// round 7
// speedup vs baseline: 1.1718x; 1.0064x over previous
#include <cuda_runtime.h>
#include <cuda_bf16.h>
#include <cstdint>

#define NN 200000
#define EE 3200000
#define BB 512
#define LL 1000

typedef unsigned long long ull;

// ------------------------ scratch (device globals, no allocs) ---------------
__device__ float g_dis[NN];
__device__ int   g_deg[NN];
__device__ float g_h[NN * 16];
__device__ float g_feat[NN * 16];
__device__ float g_agg[NN * 16];
__device__ float g_pool[BB * 16];
__device__ float g_t1[BB * 1024];
__device__ float g_xc[BB * 256];
__device__ float g_c1[BB * 32 * 331];
__device__ float g_c2[BB * 64 * 108];
__device__ float g_c3[BB * 128];
__device__ float g_f1[BB * 1024];
__device__ float g_f2[BB * 512];

// ------------------------ f32x2 helpers --------------------------------------
__device__ __forceinline__ ull pk2(float lo, float hi) {
    ull r; asm("mov.b64 %0, {%1, %2};" : "=l"(r) : "f"(lo), "f"(hi)); return r;
}
__device__ __forceinline__ float2 upk2(ull v) {
    float2 r; asm("mov.b64 {%0, %1}, %2;" : "=f"(r.x), "=f"(r.y) : "l"(v)); return r;
}
__device__ __forceinline__ void ffma2(ull& d, ull a, ull b) {
    asm("fma.rn.f32x2 %0, %1, %2, %0;" : "+l"(d) : "l"(a), "l"(b));
}

// ------------------------ graph branch --------------------------------------
__global__ void deg_kernel(const int* __restrict__ ei, int* __restrict__ deg) {
    int e = blockIdx.x * blockDim.x + threadIdx.x;
    if (e >= EE) return;
    atomicAdd(&deg[ei[EE + e]], 1);
}

__global__ void dis_kernel(const int* __restrict__ deg, float* __restrict__ dis) {
    int i = blockIdx.x * blockDim.x + threadIdx.x;
    if (i >= NN) return;
    dis[i] = rsqrtf((float)deg[i] + 1.0f);
}

// hs = dis[i] * (x @ W1)
__global__ void transform1(const float* __restrict__ x, const float* __restrict__ W,
                           const float* __restrict__ dis, float* __restrict__ hs) {
    __shared__ float Ws[16];
    int tid = threadIdx.x;
    if (tid < 16) Ws[tid] = W[tid];
    __syncthreads();
    int i = blockIdx.x * blockDim.x + tid;
    if (i >= NN) return;
    float xi[4];
#pragma unroll
    for (int f = 0; f < 4; f++) xi[f] = x[(size_t)i * 4 + f];
    float dd = dis[i];
#pragma unroll
    for (int fo = 0; fo < 4; fo++) {
        float s = 0.f;
#pragma unroll
        for (int fi = 0; fi < 4; fi++) s = fmaf(xi[fi], Ws[fi * 4 + fo], s);
        hs[(size_t)i * 4 + fo] = dd * s;
    }
}

// pure copy-scatter: agg[dst] += hs[src]
template <int F>
__global__ void scatter_kernel(const int* __restrict__ ei, const float* __restrict__ hs,
                               float* __restrict__ agg) {
    int e = blockIdx.x * blockDim.x + threadIdx.x;
    if (e >= EE) return;
    int s = __ldg(&ei[e]);
    int d = __ldg(&ei[EE + e]);
    const float4* p = reinterpret_cast<const float4*>(hs + (size_t)s * F);
    float* ad = agg + (size_t)d * F;
#pragma unroll
    for (int q = 0; q < F / 4; q++) {
        float4 m = p[q];
        asm volatile("red.global.add.v4.f32 [%0], {%1,%2,%3,%4};"
                     :: "l"(ad + q * 4), "f"(m.x), "f"(m.y), "f"(m.z), "f"(m.w)
                     : "memory");
    }
}

// feat = relu(dis*(agg+hs)+b); out = dis * (feat @ W)
template <int F, int FO>
__global__ void combine_transform(const float* __restrict__ agg, const float* __restrict__ hs,
                                  const float* __restrict__ dis, const float* __restrict__ bias,
                                  const float* __restrict__ W, float* __restrict__ out) {
    __shared__ float Ws[F * FO];
    __shared__ float bs[F];
    int tid = threadIdx.x;
    if (tid < F * FO) Ws[tid] = W[tid];
    if (tid < F) bs[tid] = bias[tid];
    __syncthreads();
    int i = blockIdx.x * blockDim.x + tid;
    if (i >= NN) return;
    float dd = dis[i];
    float v[F];
#pragma unroll
    for (int f = 0; f < F; f++)
        v[f] = fmaxf(dd * (agg[(size_t)i * F + f] + hs[(size_t)i * F + f]) + bs[f], 0.f);
#pragma unroll
    for (int fo = 0; fo < FO; fo++) {
        float s = 0.f;
#pragma unroll
        for (int f = 0; f < F; f++) s = fmaf(v[f], Ws[f * FO + fo], s);
        out[(size_t)i * FO + fo] = dd * s;
    }
}

// final GCN layer + batch max pool
__global__ void combine_pool(const float* __restrict__ agg, const float* __restrict__ hs,
                             const float* __restrict__ dis, const float* __restrict__ bias,
                             const int* __restrict__ batch, float* __restrict__ pool) {
    __shared__ float bs[16];
    int tid = threadIdx.x;
    if (tid < 16) bs[tid] = bias[tid];
    __syncthreads();
    int i = blockIdx.x * blockDim.x + tid;
    if (i >= NN) return;
    float dd = dis[i];
    float v[16];
#pragma unroll
    for (int f = 0; f < 16; f++)
        v[f] = fmaxf(dd * (agg[(size_t)i * 16 + f] + hs[(size_t)i * 16 + f]) + bs[f], 0.f);
    int bb = batch[i];
    unsigned m = __activemask();
    bool uni = false;
    if (m == 0xffffffffu) {
        int bb0 = __shfl_sync(0xffffffffu, bb, 0);
        uni = __all_sync(0xffffffffu, bb == bb0);
    }
    int* p = reinterpret_cast<int*>(pool + (size_t)bb * 16);
    if (uni) {
#pragma unroll
        for (int f = 0; f < 16; f++) {
            float t = v[f];
#pragma unroll
            for (int o = 16; o; o >>= 1) t = fmaxf(t, __shfl_xor_sync(0xffffffffu, t, o));
            v[f] = t;
        }
        if ((tid & 31) == 0)
#pragma unroll
            for (int f = 0; f < 16; f++) atomicMax(&p[f], __float_as_int(v[f]));
    } else {
#pragma unroll
        for (int f = 0; f < 16; f++) atomicMax(&p[f], __float_as_int(v[f]));
    }
}

// ------------------------ generic GEMM (f32x2) -------------------------------
__global__ void gemm_kernel(const float* __restrict__ A, const float* __restrict__ W,
                            const float* __restrict__ bias, float* __restrict__ C,
                            int M, int K, int Nc, int ldc, int coloff, int relu) {
    const int BM = 64, BN = 64, BK = 8;
    __shared__ __align__(16) float As[BK][BM];
    __shared__ __align__(16) float Bs[BK][BN];
    int tid = threadIdx.x;
    int tc = tid & 15, tr = tid >> 4;
    int brow = blockIdx.y * BM, bcol = blockIdx.x * BN;
    ull acc[4][2] = {};
    for (int k0 = 0; k0 < K; k0 += BK) {
        for (int i = tid; i < BM * BK; i += 256) {
            int kk = i & 7, m = i >> 3;
            int gr = brow + m, gc = k0 + kk;
            As[kk][m] = (gr < M && gc < K) ? A[(size_t)gr * K + gc] : 0.f;
        }
        for (int i = tid; i < BN * BK; i += 256) {
            int n = i & 63, kk = i >> 6;
            int gc = bcol + n, gr = k0 + kk;
            Bs[kk][n] = (gr < K && gc < Nc) ? W[(size_t)gr * Nc + gc] : 0.f;
        }
        __syncthreads();
#pragma unroll
        for (int kk = 0; kk < BK; kk++) {
            ull b0 = *reinterpret_cast<const ull*>(&Bs[kk][tc * 4]);
            ull b1 = *reinterpret_cast<const ull*>(&Bs[kk][tc * 4 + 2]);
            float4 av = *reinterpret_cast<const float4*>(&As[kk][tr * 4]);
            float aa[4] = {av.x, av.y, av.z, av.w};
#pragma unroll
            for (int u = 0; u < 4; u++) {
                ull a2 = pk2(aa[u], aa[u]);
                ffma2(acc[u][0], b0, a2);
                ffma2(acc[u][1], b1, a2);
            }
        }
        __syncthreads();
    }
#pragma unroll
    for (int u = 0; u < 4; u++) {
        int r = brow + tr * 4 + u;
        if (r >= M) continue;
#pragma unroll
        for (int v2 = 0; v2 < 2; v2++) {
            float2 pv = upk2(acc[u][v2]);
            float vals[2] = {pv.x, pv.y};
#pragma unroll
            for (int w = 0; w < 2; w++) {
                int c = bcol + tc * 4 + v2 * 2 + w;
                if (c >= Nc) continue;
                float val = vals[w] + bias[c];
                if (relu) val = fmaxf(val, 0.f);
                C[(size_t)r * ldc + coloff + c] = val;
            }
        }
    }
}

// ------------------------ conv inner helpers --------------------------------
// Load 16 even pairs + 16 odd pairs (xB = xA shifted by one position).
__device__ __forceinline__ void load_eo(const float* __restrict__ xA,
                                        const float* __restrict__ xB, ull e[8], ull o[8]) {
    const ulonglong2* pA = reinterpret_cast<const ulonglong2*>(xA);
    const ulonglong2* pB = reinterpret_cast<const ulonglong2*>(xB);
#pragma unroll
    for (int i = 0; i < 4; i++) {
        ulonglong2 va = pA[i]; e[2 * i] = va.x; e[2 * i + 1] = va.y;
        ulonglong2 vb = pB[i]; o[2 * i] = vb.x; o[2 * i + 1] = vb.y;
    }
}

// 1 output channel, weight smem stride 33 (conflict-free padded)
__device__ __forceinline__ void ic_upd_1oc(const float* __restrict__ xA,
                                           const float* __restrict__ xB,
                                           const float* __restrict__ w, ull a0[5]) {
    ull e[8], o[8];
    load_eo(xA, xB, e, o);
#pragma unroll
    for (int k = 0; k < 8; k++) {
        float wv = w[k * 33];
        ull w2 = pk2(wv, wv);
        const ull* xpp = (k & 1) ? &o[k >> 1] : &e[k >> 1];
#pragma unroll
        for (int j = 0; j < 5; j++) ffma2(a0[j], xpp[j], w2);
    }
}

// 2 output channels via pre-duplicated (w,w) pairs. wp pre-offset by 2*tx.
// Per k: one LDS.64 for oc=tx, one for oc=tx+32 (offset +64 floats). Row
// stride = 130 floats (128 + 2 pad -> conflict-free, 8B aligned). Zero pk2.
__device__ __forceinline__ void ic_upd_2oc_w2(const float* __restrict__ xA,
                                              const float* __restrict__ xB,
                                              const float* __restrict__ wp,
                                              ull a0[5], ull a1[5]) {
    ull e[8], o[8];
    load_eo(xA, xB, e, o);
#pragma unroll
    for (int k = 0; k < 8; k++) {
        ull w20 = *reinterpret_cast<const ull*>(wp + k * 130);
        ull w21 = *reinterpret_cast<const ull*>(wp + k * 130 + 64);
        const ull* xpp = (k & 1) ? &o[k >> 1] : &e[k >> 1];
#pragma unroll
        for (int j = 0; j < 5; j++) {
            ffma2(a0[j], xpp[j], w20);
            ffma2(a1[j], xpp[j], w21);
        }
    }
}

__device__ __forceinline__ void unpack9(const ull acc[5], float a[9]) {
#pragma unroll
    for (int j = 0; j < 4; j++) {
        float2 t = upk2(acc[j]);
        a[2 * j] = t.x; a[2 * j + 1] = t.y;
    }
    a[8] = upk2(acc[4]).x;
}

// conv1: target [B,L,5] -> conv(k=8)+relu+maxpool3 -> [B,32,331]
__global__ void conv1_kernel(const float* __restrict__ tgt, const float* __restrict__ K1,
                             const float* __restrict__ cb1, float* __restrict__ out) {
    __shared__ __align__(16) float inA[5 * 8 * 16];
    __shared__ __align__(16) float inB[5 * 8 * 16];
    __shared__ float w_s[40 * 33];   // [(ic*8+k)*33 + oc]
    __shared__ float b_s[32];
    int b = blockIdx.x;
    int g0 = blockIdx.y * 8;
    int tx = threadIdx.x, ty = threadIdx.y;
    int tid = ty * 32 + tx;
    int L0 = g0 * 9;
    for (int i = tid; i < 640; i += 256) {
        int c = i >> 7, t = (i >> 4) & 7, j = i & 15;
        int l = L0 + t * 9 + j;
        inA[i] = (l < LL) ? tgt[(size_t)b * (LL * 5) + l * 5 + c] : 0.f;
        inB[i] = (l + 1 < LL) ? tgt[(size_t)b * (LL * 5) + (l + 1) * 5 + c] : 0.f;
    }
    for (int i = tid; i < 2048; i += 256) {
        int oc = i >> 6, r = i & 63;
        if (r < 40) w_s[r * 33 + oc] = K1[oc * 40 + r];
    }
    if (tid < 32) b_s[tid] = cb1[tid];
    __syncthreads();

    ull acc[5] = {};
#pragma unroll
    for (int ic = 0; ic < 5; ic++)
        ic_upd_1oc(&inA[(ic * 8 + ty) * 16], &inB[(ic * 8 + ty) * 16],
                   &w_s[ic * 8 * 33 + tx], acc);
    float a[9]; unpack9(acc, a);
    float bb = b_s[tx];
    int grp = g0 + ty;
#pragma unroll
    for (int p = 0; p < 3; p++) {
        int po = grp * 3 + p;
        if (po < 331) {
            float v = fmaxf(fmaxf(a[3 * p], a[3 * p + 1]), a[3 * p + 2]) + bb;
            out[((size_t)b * 32 + tx) * 331 + po] = fmaxf(v, 0.f);
        }
    }
}

// conv2: [B,32,331] -> conv(k=8)+relu+pool3 -> [B,64,108]
// Weights tiled over ic (4 ic/tile), duplicated as (w,w) pairs.
#define CONV2_SMEM ((4096 + 4096 + 32 * 130 + 64) * 4)
__global__ void conv2_kernel(const float* __restrict__ c1, const float* __restrict__ K2,
                             const float* __restrict__ cb2, float* __restrict__ out) {
    extern __shared__ __align__(16) float sm2[];
    float* inA = sm2;                 // 32*8*16
    float* inB = sm2 + 4096;
    float* w2 = sm2 + 8192;           // tile: 32 rows x 130 (oc pairs)
    float* b_s = w2 + 32 * 130;
    int b = blockIdx.x;
    int g0 = blockIdx.y * 8;
    int tx = threadIdx.x, ty = threadIdx.y;
    int tid = ty * 32 + tx;
    int L0 = g0 * 9;
    for (int i = tid; i < 4096; i += 256) {
        int ic = i >> 7, t = (i >> 4) & 7, j = i & 15;
        int l = L0 + t * 9 + j;
        const float* row = c1 + ((size_t)b * 32 + ic) * 331;
        inA[i] = (l < 331) ? row[l] : 0.f;
        inB[i] = (l + 1 < 331) ? row[l + 1] : 0.f;
    }
    if (tid < 64) b_s[tid] = cb2[tid];

    int grp = g0 + ty;
    ull a0[5] = {}, a1[5] = {};
    const float* wp = w2 + 2 * tx;
    for (int t = 0; t < 8; t++) {          // 8 tiles x 4 ic
        __syncthreads();                   // protect prior tile reads (& input on t=0)
        for (int i = tid; i < 2048; i += 256) {
            int rr = i & 31, oc = i >> 5;  // coalesced LDG over rr
            float v = K2[(size_t)oc * 256 + t * 32 + rr];
            *reinterpret_cast<float2*>(&w2[rr * 130 + 2 * oc]) = make_float2(v, v);
        }
        __syncthreads();
#pragma unroll
        for (int ic2 = 0; ic2 < 4; ic2++) {
            int ic = t * 4 + ic2;
            ic_upd_2oc_w2(&inA[(ic * 8 + ty) * 16], &inB[(ic * 8 + ty) * 16],
                          wp + ic2 * 8 * 130, a0, a1);
        }
    }
    if (grp < 36) {
        float v0[9], v1[9]; unpack9(a0, v0); unpack9(a1, v1);
        float bb0 = b_s[tx], bb1 = b_s[tx + 32];
        float* o0 = out + ((size_t)b * 64 + tx) * 108;
        float* o1 = out + ((size_t)b * 64 + tx + 32) * 108;
#pragma unroll
        for (int p = 0; p < 3; p++) {
            int po = grp * 3 + p;
            o0[po] = fmaxf(fmaxf(fmaxf(v0[3 * p], v0[3 * p + 1]), v0[3 * p + 2]) + bb0, 0.f);
            o1[po] = fmaxf(fmaxf(fmaxf(v1[3 * p], v1[3 * p + 1]), v1[3 * p + 2]) + bb1, 0.f);
        }
    }
}

// conv3: [B,64,108] -> conv+relu+pool3 -> mean33 -> [B,128]
// Weights tiled over ic (4 ic/tile), duplicated pairs; 2 blocks/SM.
#define CONV3_SMEM ((11264 + 11264 + 32 * 130 + 64) * 4)
__global__ void __launch_bounds__(352, 2) conv3_kernel(
        const float* __restrict__ c2, const float* __restrict__ K3,
        const float* __restrict__ cb3, float* __restrict__ c3) {
    extern __shared__ __align__(16) float sm3[];
    float* inA = sm3;                  // 64*11*16
    float* inB = sm3 + 11264;
    float* w2 = sm3 + 22528;           // tile: 32 rows x 130
    float* b_s = w2 + 32 * 130;
    int b = blockIdx.x;
    int ocz = blockIdx.y;              // 0,1 -> oc base 0,64
    int tx = threadIdx.x, ty = threadIdx.y;
    int tid = ty * 32 + tx;            // 352 threads
    for (int i = tid; i < 11264; i += 352) {
        int ic = i / 176, r = i % 176, t = r / 16, j = r % 16;
        int l = t * 9 + j;
        const float* row = c2 + (size_t)b * 6912 + ic * 108;
        inA[i] = row[l];
        inB[i] = (l + 1 < 108) ? row[l + 1] : 0.f;
    }
    if (tid < 64) b_s[tid] = cb3[ocz * 64 + tid];

    ull a0[5] = {}, a1[5] = {};
    const float* wp = w2 + 2 * tx;
    for (int t = 0; t < 16; t++) {         // 16 tiles x 4 ic
        __syncthreads();
        for (int i = tid; i < 2048; i += 352) {
            int rr = i & 31, oc = i >> 5;
            float v = K3[((size_t)(ocz * 64 + oc)) * 512 + t * 32 + rr];
            *reinterpret_cast<float2*>(&w2[rr * 130 + 2 * oc]) = make_float2(v, v);
        }
        __syncthreads();
#pragma unroll
        for (int ic2 = 0; ic2 < 4; ic2++) {
            int ic = t * 4 + ic2;
            ic_upd_2oc_w2(&inA[(ic * 11 + ty) * 16], &inB[(ic * 11 + ty) * 16],
                          wp + ic2 * 8 * 130, a0, a1);
        }
    }
    float v0[9], v1[9]; unpack9(a0, v0); unpack9(a1, v1);
    float bb0 = b_s[tx], bb1 = b_s[tx + 32];
    float s0 = 0.f, s1 = 0.f;
#pragma unroll
    for (int p = 0; p < 3; p++) {
        s0 += fmaxf(fmaxf(fmaxf(v0[3 * p], v0[3 * p + 1]), v0[3 * p + 2]) + bb0, 0.f);
        s1 += fmaxf(fmaxf(fmaxf(v1[3 * p], v1[3 * p + 1]), v1[3 * p + 2]) + bb1, 0.f);
    }
    atomicAdd(&c3[(size_t)b * 128 + ocz * 64 + tx], s0 * (1.0f / 33.0f));
    atomicAdd(&c3[(size_t)b * 128 + ocz * 64 + tx + 32], s1 * (1.0f / 33.0f));
}

// ------------------------ stream fork/join context --------------------------
struct Ctx {
    cudaStream_t s2 = nullptr;
    cudaEvent_t eF = nullptr, eJ = nullptr;
    bool ok = false;
    Ctx() {
        ok = (cudaStreamCreateWithFlags(&s2, cudaStreamNonBlocking) == cudaSuccess) &&
             (cudaEventCreateWithFlags(&eF, cudaEventDisableTiming) == cudaSuccess) &&
             (cudaEventCreateWithFlags(&eJ, cudaEventDisableTiming) == cudaSuccess);
    }
};
static Ctx g_ctx;

// ------------------------ host orchestration --------------------------------
extern "C" void kernel_launch(void* const* d_in, const int* in_sizes, int n_in,
                              void* d_out, int out_size) {
    const float* x    = (const float*)d_in[0];
    const int*   ei   = (const int*)d_in[1];
    const int*   batch= (const int*)d_in[2];
    const float* tgt  = (const float*)d_in[3];
    const float* W1 = (const float*)d_in[4];   const float* b1 = (const float*)d_in[5];
    const float* W2 = (const float*)d_in[6];   const float* b2 = (const float*)d_in[7];
    const float* W3 = (const float*)d_in[8];   const float* b3 = (const float*)d_in[9];
    const float* Wg1= (const float*)d_in[10];  const float* bg1= (const float*)d_in[11];
    const float* Wg2= (const float*)d_in[12];  const float* bg2= (const float*)d_in[13];
    const float* K1 = (const float*)d_in[14];  const float* cb1= (const float*)d_in[15];
    const float* K2 = (const float*)d_in[16];  const float* cb2= (const float*)d_in[17];
    const float* K3 = (const float*)d_in[18];  const float* cb3= (const float*)d_in[19];
    const float* Wxt= (const float*)d_in[20];  const float* bxt= (const float*)d_in[21];
    const float* Wf1= (const float*)d_in[22];  const float* bf1= (const float*)d_in[23];
    const float* Wf2= (const float*)d_in[24];  const float* bf2= (const float*)d_in[25];
    const float* Wo = (const float*)d_in[26];  const float* bo = (const float*)d_in[27];
    float* out = (float*)d_out;

    float *p_dis, *p_h, *p_feat, *p_agg, *p_pool, *p_t1, *p_xc, *p_c1, *p_c2, *p_c3, *p_f1, *p_f2;
    int* p_deg;
    cudaGetSymbolAddress((void**)&p_dis, g_dis);
    cudaGetSymbolAddress((void**)&p_deg, g_deg);
    cudaGetSymbolAddress((void**)&p_h, g_h);
    cudaGetSymbolAddress((void**)&p_feat, g_feat);
    cudaGetSymbolAddress((void**)&p_agg, g_agg);
    cudaGetSymbolAddress((void**)&p_pool, g_pool);
    cudaGetSymbolAddress((void**)&p_t1, g_t1);
    cudaGetSymbolAddress((void**)&p_xc, g_xc);
    cudaGetSymbolAddress((void**)&p_c1, g_c1);
    cudaGetSymbolAddress((void**)&p_c2, g_c2);
    cudaGetSymbolAddress((void**)&p_c3, g_c3);
    cudaGetSymbolAddress((void**)&p_f1, g_f1);
    cudaGetSymbolAddress((void**)&p_f2, g_f2);

    const int TPB = 256;
    const int gE = (EE + TPB - 1) / TPB;
    const int gN = (NN + TPB - 1) / TPB;

    bool fork = g_ctx.ok;
    cudaStream_t sg = fork ? g_ctx.s2 : (cudaStream_t)0;

    if (fork) {
        cudaEventRecord(g_ctx.eF, 0);
        cudaStreamWaitEvent(sg, g_ctx.eF, 0);
    }

    cudaFuncSetAttribute(conv2_kernel, cudaFuncAttributeMaxDynamicSharedMemorySize, CONV2_SMEM);
    cudaFuncSetAttribute(conv3_kernel, cudaFuncAttributeMaxDynamicSharedMemorySize, CONV3_SMEM);

    // Submission order: conv3 is the 6th launch (ncu -s 5 -c 1 window).
    cudaMemsetAsync(p_deg, 0, NN * sizeof(int), sg);                                 // 1
    deg_kernel<<<gE, TPB, 0, sg>>>(ei, p_deg);                                       // 2
    conv1_kernel<<<dim3(BB, 14), dim3(32, 8)>>>(tgt, K1, cb1, p_c1);                 // 3
    cudaMemsetAsync(p_c3, 0, BB * 128 * sizeof(float));                              // 4
    conv2_kernel<<<dim3(BB, 5), dim3(32, 8), CONV2_SMEM>>>(p_c1, K2, cb2, p_c2);     // 5
    conv3_kernel<<<dim3(BB, 2), dim3(32, 11), CONV3_SMEM>>>(p_c2, K3, cb3, p_c3);    // 6 <- profiled
    gemm_kernel<<<dim3(2, 8), 256>>>(p_c3, Wxt, bxt, p_xc, BB, 128, 128, 256, 128, 1);

    // ---- graph branch (stream sg) ----
    dis_kernel<<<gN, TPB, 0, sg>>>(p_deg, p_dis);
    transform1<<<gN, TPB, 0, sg>>>(x, W1, p_dis, p_h);
    cudaMemsetAsync(p_agg, 0, (size_t)NN * 4 * sizeof(float), sg);
    scatter_kernel<4><<<gE, TPB, 0, sg>>>(ei, p_h, p_agg);
    combine_transform<4, 8><<<gN, TPB, 0, sg>>>(p_agg, p_h, p_dis, b1, W2, p_feat);

    cudaMemsetAsync(p_agg, 0, (size_t)NN * 8 * sizeof(float), sg);
    scatter_kernel<8><<<gE, TPB, 0, sg>>>(ei, p_feat, p_agg);
    combine_transform<8, 16><<<gN, TPB, 0, sg>>>(p_agg, p_feat, p_dis, b2, W3, p_h);

    cudaMemsetAsync(p_agg, 0, (size_t)NN * 16 * sizeof(float), sg);
    scatter_kernel<16><<<gE, TPB, 0, sg>>>(ei, p_h, p_agg);
    cudaMemsetAsync(p_pool, 0, BB * 16 * sizeof(float), sg);
    combine_pool<<<gN, TPB, 0, sg>>>(p_agg, p_h, p_dis, b3, batch, p_pool);

    gemm_kernel<<<dim3(16, 8), 256, 0, sg>>>(p_pool, Wg1, bg1, p_t1, BB, 16, 1024, 1024, 0, 1);
    gemm_kernel<<<dim3(2, 8), 256, 0, sg>>>(p_t1, Wg2, bg2, p_xc, BB, 1024, 128, 256, 0, 0);
    if (fork) cudaEventRecord(g_ctx.eJ, sg);

    // ---- join + fusion head (stream 0) ----
    if (fork) cudaStreamWaitEvent(0, g_ctx.eJ, 0);
    gemm_kernel<<<dim3(16, 8), 256>>>(p_xc, Wf1, bf1, p_f1, BB, 256, 1024, 1024, 0, 1);
    gemm_kernel<<<dim3(8, 8), 256>>>(p_f1, Wf2, bf2, p_f2, BB, 1024, 512, 512, 0, 1);
    gemm_kernel<<<dim3(1, 8), 256>>>(p_f2, Wo, bo, out, BB, 512, 2, 2, 0, 0);
}

// round 8
// speedup vs baseline: 1.1842x; 1.0105x over previous
#include <cuda_runtime.h>
#include <cuda_bf16.h>
#include <cstdint>

#define NN 200000
#define EE 3200000
#define BB 512
#define LL 1000

typedef unsigned long long ull;

// ------------------------ scratch (device globals, no allocs) ---------------
__device__ float g_dis[NN];
__device__ int   g_deg[NN];
__device__ float g_h[NN * 16];
__device__ float g_feat[NN * 16];
__device__ float g_agg[NN * 16];
__device__ float g_pool[BB * 16];
__device__ float g_t1[BB * 1024];
__device__ float g_xc[BB * 256];
__device__ float g_c1[BB * 32 * 331];
__device__ float g_c2[BB * 64 * 108];
__device__ float g_c3[BB * 128];
__device__ float g_f1[BB * 1024];
__device__ float g_f2[BB * 512];

// ------------------------ f32x2 helpers --------------------------------------
__device__ __forceinline__ ull pk2(float lo, float hi) {
    ull r; asm("mov.b64 %0, {%1, %2};" : "=l"(r) : "f"(lo), "f"(hi)); return r;
}
__device__ __forceinline__ float2 upk2(ull v) {
    float2 r; asm("mov.b64 {%0, %1}, %2;" : "=f"(r.x), "=f"(r.y) : "l"(v)); return r;
}
__device__ __forceinline__ void ffma2(ull& d, ull a, ull b) {
    asm("fma.rn.f32x2 %0, %1, %2, %0;" : "+l"(d) : "l"(a), "l"(b));
}

// ------------------------ graph branch --------------------------------------
__global__ void deg_kernel(const int* __restrict__ ei, int* __restrict__ deg) {
    int e = blockIdx.x * blockDim.x + threadIdx.x;
    if (e >= EE) return;
    atomicAdd(&deg[ei[EE + e]], 1);
}

__global__ void dis_kernel(const int* __restrict__ deg, float* __restrict__ dis) {
    int i = blockIdx.x * blockDim.x + threadIdx.x;
    if (i >= NN) return;
    dis[i] = rsqrtf((float)deg[i] + 1.0f);
}

// hs = dis[i] * (x @ W1)
__global__ void transform1(const float* __restrict__ x, const float* __restrict__ W,
                           const float* __restrict__ dis, float* __restrict__ hs) {
    __shared__ float Ws[16];
    int tid = threadIdx.x;
    if (tid < 16) Ws[tid] = W[tid];
    __syncthreads();
    int i = blockIdx.x * blockDim.x + tid;
    if (i >= NN) return;
    float xi[4];
#pragma unroll
    for (int f = 0; f < 4; f++) xi[f] = x[(size_t)i * 4 + f];
    float dd = dis[i];
#pragma unroll
    for (int fo = 0; fo < 4; fo++) {
        float s = 0.f;
#pragma unroll
        for (int fi = 0; fi < 4; fi++) s = fmaf(xi[fi], Ws[fi * 4 + fo], s);
        hs[(size_t)i * 4 + fo] = dd * s;
    }
}

// pure copy-scatter: agg[dst] += hs[src]
template <int F>
__global__ void scatter_kernel(const int* __restrict__ ei, const float* __restrict__ hs,
                               float* __restrict__ agg) {
    int e = blockIdx.x * blockDim.x + threadIdx.x;
    if (e >= EE) return;
    int s = __ldg(&ei[e]);
    int d = __ldg(&ei[EE + e]);
    const float4* p = reinterpret_cast<const float4*>(hs + (size_t)s * F);
    float* ad = agg + (size_t)d * F;
#pragma unroll
    for (int q = 0; q < F / 4; q++) {
        float4 m = p[q];
        asm volatile("red.global.add.v4.f32 [%0], {%1,%2,%3,%4};"
                     :: "l"(ad + q * 4), "f"(m.x), "f"(m.y), "f"(m.z), "f"(m.w)
                     : "memory");
    }
}

// feat = relu(dis*(agg+hs)+b); out = dis * (feat @ W)
template <int F, int FO>
__global__ void combine_transform(const float* __restrict__ agg, const float* __restrict__ hs,
                                  const float* __restrict__ dis, const float* __restrict__ bias,
                                  const float* __restrict__ W, float* __restrict__ out) {
    __shared__ float Ws[F * FO];
    __shared__ float bs[F];
    int tid = threadIdx.x;
    if (tid < F * FO) Ws[tid] = W[tid];
    if (tid < F) bs[tid] = bias[tid];
    __syncthreads();
    int i = blockIdx.x * blockDim.x + tid;
    if (i >= NN) return;
    float dd = dis[i];
    float v[F];
#pragma unroll
    for (int f = 0; f < F; f++)
        v[f] = fmaxf(dd * (agg[(size_t)i * F + f] + hs[(size_t)i * F + f]) + bs[f], 0.f);
#pragma unroll
    for (int fo = 0; fo < FO; fo++) {
        float s = 0.f;
#pragma unroll
        for (int f = 0; f < F; f++) s = fmaf(v[f], Ws[f * FO + fo], s);
        out[(size_t)i * FO + fo] = dd * s;
    }
}

// final GCN layer + batch max pool
__global__ void combine_pool(const float* __restrict__ agg, const float* __restrict__ hs,
                             const float* __restrict__ dis, const float* __restrict__ bias,
                             const int* __restrict__ batch, float* __restrict__ pool) {
    __shared__ float bs[16];
    int tid = threadIdx.x;
    if (tid < 16) bs[tid] = bias[tid];
    __syncthreads();
    int i = blockIdx.x * blockDim.x + tid;
    if (i >= NN) return;
    float dd = dis[i];
    float v[16];
#pragma unroll
    for (int f = 0; f < 16; f++)
        v[f] = fmaxf(dd * (agg[(size_t)i * 16 + f] + hs[(size_t)i * 16 + f]) + bs[f], 0.f);
    int bb = batch[i];
    unsigned m = __activemask();
    bool uni = false;
    if (m == 0xffffffffu) {
        int bb0 = __shfl_sync(0xffffffffu, bb, 0);
        uni = __all_sync(0xffffffffu, bb == bb0);
    }
    int* p = reinterpret_cast<int*>(pool + (size_t)bb * 16);
    if (uni) {
#pragma unroll
        for (int f = 0; f < 16; f++) {
            float t = v[f];
#pragma unroll
            for (int o = 16; o; o >>= 1) t = fmaxf(t, __shfl_xor_sync(0xffffffffu, t, o));
            v[f] = t;
        }
        if ((tid & 31) == 0)
#pragma unroll
            for (int f = 0; f < 16; f++) atomicMax(&p[f], __float_as_int(v[f]));
    } else {
#pragma unroll
        for (int f = 0; f < 16; f++) atomicMax(&p[f], __float_as_int(v[f]));
    }
}

// ------------------------ generic GEMM (f32x2) -------------------------------
__global__ void gemm_kernel(const float* __restrict__ A, const float* __restrict__ W,
                            const float* __restrict__ bias, float* __restrict__ C,
                            int M, int K, int Nc, int ldc, int coloff, int relu) {
    const int BM = 64, BN = 64, BK = 8;
    __shared__ __align__(16) float As[BK][BM];
    __shared__ __align__(16) float Bs[BK][BN];
    int tid = threadIdx.x;
    int tc = tid & 15, tr = tid >> 4;
    int brow = blockIdx.y * BM, bcol = blockIdx.x * BN;
    ull acc[4][2] = {};
    for (int k0 = 0; k0 < K; k0 += BK) {
        for (int i = tid; i < BM * BK; i += 256) {
            int kk = i & 7, m = i >> 3;
            int gr = brow + m, gc = k0 + kk;
            As[kk][m] = (gr < M && gc < K) ? A[(size_t)gr * K + gc] : 0.f;
        }
        for (int i = tid; i < BN * BK; i += 256) {
            int n = i & 63, kk = i >> 6;
            int gc = bcol + n, gr = k0 + kk;
            Bs[kk][n] = (gr < K && gc < Nc) ? W[(size_t)gr * Nc + gc] : 0.f;
        }
        __syncthreads();
#pragma unroll
        for (int kk = 0; kk < BK; kk++) {
            ull b0 = *reinterpret_cast<const ull*>(&Bs[kk][tc * 4]);
            ull b1 = *reinterpret_cast<const ull*>(&Bs[kk][tc * 4 + 2]);
            float4 av = *reinterpret_cast<const float4*>(&As[kk][tr * 4]);
            float aa[4] = {av.x, av.y, av.z, av.w};
#pragma unroll
            for (int u = 0; u < 4; u++) {
                ull a2 = pk2(aa[u], aa[u]);
                ffma2(acc[u][0], b0, a2);
                ffma2(acc[u][1], b1, a2);
            }
        }
        __syncthreads();
    }
#pragma unroll
    for (int u = 0; u < 4; u++) {
        int r = brow + tr * 4 + u;
        if (r >= M) continue;
#pragma unroll
        for (int v2 = 0; v2 < 2; v2++) {
            float2 pv = upk2(acc[u][v2]);
            float vals[2] = {pv.x, pv.y};
#pragma unroll
            for (int w = 0; w < 2; w++) {
                int c = bcol + tc * 4 + v2 * 2 + w;
                if (c >= Nc) continue;
                float val = vals[w] + bias[c];
                if (relu) val = fmaxf(val, 0.f);
                C[(size_t)r * ldc + coloff + c] = val;
            }
        }
    }
}

// ------------------------ conv inner helpers --------------------------------
// xA: 20 contiguous 16B-aligned floats (positions p..p+19, zero padded).
// e[j] = (x[2j], x[2j+1]) j=0..9 from 5 LDS.128; o[j] derived by register movs.
__device__ __forceinline__ void load_e10(const float* __restrict__ xA, ull e[10]) {
    const ulonglong2* pA = reinterpret_cast<const ulonglong2*>(xA);
#pragma unroll
    for (int i = 0; i < 5; i++) {
        ulonglong2 va = pA[i]; e[2 * i] = va.x; e[2 * i + 1] = va.y;
    }
}
__device__ __forceinline__ void make_o8(const ull e[10], ull o[8]) {
#pragma unroll
    for (int j = 0; j < 8; j++)
        o[j] = (e[j] >> 32) | (e[j + 1] << 32);   // {hi(e[j]), lo(e[j+1])} -> 2 movs
}

// 1 oc (w stride 33), scalar weights + pk2
__device__ __forceinline__ void ic_upd_1oc(const float* __restrict__ xA,
                                           const float* __restrict__ w, ull a0[5]) {
    ull e[10], o[8];
    load_e10(xA, e); make_o8(e, o);
#pragma unroll
    for (int k = 0; k < 8; k++) {
        float wv = w[k * 33];
        ull w2 = pk2(wv, wv);
        const ull* xpp = (k & 1) ? &o[k >> 1] : &e[k >> 1];
#pragma unroll
        for (int j = 0; j < 5; j++) ffma2(a0[j], xpp[j], w2);
    }
}

// 2 oc (tx, tx+32) from a scalar weight tile, row stride 65 (padded, cf-free)
__device__ __forceinline__ void ic_upd_2oc(const float* __restrict__ xA,
                                           const float* __restrict__ w, int tx,
                                           ull a0[5], ull a1[5]) {
    ull e[10], o[8];
    load_e10(xA, e); make_o8(e, o);
#pragma unroll
    for (int k = 0; k < 8; k++) {
        float w0 = w[k * 65 + tx];
        float w1 = w[k * 65 + tx + 32];
        ull w20 = pk2(w0, w0);
        ull w21 = pk2(w1, w1);
        const ull* xpp = (k & 1) ? &o[k >> 1] : &e[k >> 1];
#pragma unroll
        for (int j = 0; j < 5; j++) {
            ffma2(a0[j], xpp[j], w20);
            ffma2(a1[j], xpp[j], w21);
        }
    }
}

__device__ __forceinline__ void unpack9(const ull acc[5], float a[9]) {
#pragma unroll
    for (int j = 0; j < 4; j++) {
        float2 t = upk2(acc[j]);
        a[2 * j] = t.x; a[2 * j + 1] = t.y;
    }
    a[8] = upk2(acc[4]).x;
}

// conv1: target [B,L,5] -> conv(k=8)+relu+maxpool3 -> [B,32,331]
__global__ void conv1_kernel(const float* __restrict__ tgt, const float* __restrict__ K1,
                             const float* __restrict__ cb1, float* __restrict__ out) {
    __shared__ __align__(16) float inA[5 * 8 * 20];
    __shared__ float w_s[40 * 33];
    __shared__ float b_s[32];
    int b = blockIdx.x;
    int g0 = blockIdx.y * 8;
    int tx = threadIdx.x, ty = threadIdx.y;
    int tid = ty * 32 + tx;
    int L0 = g0 * 9;
    for (int i = tid; i < 800; i += 256) {
        int c = i / 160, r = i % 160, t = r / 20, j = r % 20;
        int l = L0 + t * 9 + j;
        inA[i] = (l < LL) ? tgt[(size_t)b * (LL * 5) + l * 5 + c] : 0.f;
    }
    for (int i = tid; i < 2048; i += 256) {
        int oc = i >> 6, r = i & 63;
        if (r < 40) w_s[r * 33 + oc] = K1[oc * 40 + r];
    }
    if (tid < 32) b_s[tid] = cb1[tid];
    __syncthreads();

    ull acc[5] = {};
#pragma unroll
    for (int ic = 0; ic < 5; ic++)
        ic_upd_1oc(&inA[(ic * 8 + ty) * 20], &w_s[ic * 8 * 33 + tx], acc);
    float a[9]; unpack9(acc, a);
    float bb = b_s[tx];
    int grp = g0 + ty;
#pragma unroll
    for (int p = 0; p < 3; p++) {
        int po = grp * 3 + p;
        if (po < 331) {
            float v = fmaxf(fmaxf(a[3 * p], a[3 * p + 1]), a[3 * p + 2]) + bb;
            out[((size_t)b * 32 + tx) * 331 + po] = fmaxf(v, 0.f);
        }
    }
}

// conv2: [B,32,331] -> conv(k=8)+relu+pool3 -> [B,64,108]
// 8 weight tiles (4 ic each), double-buffered smem, reg-prefetched LDG.
#define C2_WTILE (32 * 65)
#define CONV2_SMEM ((5120 + 2 * C2_WTILE + 64) * 4)
__global__ void conv2_kernel(const float* __restrict__ c1, const float* __restrict__ K2,
                             const float* __restrict__ cb2, float* __restrict__ out) {
    extern __shared__ __align__(16) float sm2[];
    float* inA = sm2;                 // 32*8*20
    float* w2 = sm2 + 5120;           // 2 x (32 x 65)
    float* b_s = w2 + 2 * C2_WTILE;
    int b = blockIdx.x;
    int g0 = blockIdx.y * 8;
    int tx = threadIdx.x, ty = threadIdx.y;
    int tid = ty * 32 + tx;
    int L0 = g0 * 9;
    for (int i = tid; i < 5120; i += 256) {
        int ic = i / 160, r = i % 160, t = r / 20, j = r % 20;
        int l = L0 + t * 9 + j;
        inA[i] = (l < 331) ? c1[((size_t)b * 32 + ic) * 331 + l] : 0.f;
    }
    if (tid < 64) b_s[tid] = cb2[tid];

    // weight pipeline: 8 slots/thread (2048/256)
    float v[8];
    int rr = tid & 31, oc = tid >> 5;    // slot u: (rr, oc + 8u)
#define C2_LDG(t) { _Pragma("unroll") for (int u = 0; u < 8; u++) \
        v[u] = K2[(size_t)(oc + 8 * u) * 256 + (t) * 32 + rr]; }
#define C2_STS(buf) { _Pragma("unroll") for (int u = 0; u < 8; u++) \
        (buf)[rr * 65 + oc + 8 * u] = v[u]; }
    C2_LDG(0); C2_STS(w2); C2_LDG(1);
    __syncthreads();

    int grp = g0 + ty;
    ull a0[5] = {}, a1[5] = {};
    for (int t = 0; t < 8; t++) {
        float* cur = w2 + (t & 1) * C2_WTILE;
        if (t + 1 < 8) { C2_STS(w2 + ((t + 1) & 1) * C2_WTILE); }
        if (t + 2 < 8) { C2_LDG(t + 2); }
#pragma unroll
        for (int ic2 = 0; ic2 < 4; ic2++) {
            int ic = t * 4 + ic2;
            ic_upd_2oc(&inA[(ic * 8 + ty) * 20], &cur[ic2 * 8 * 65], tx, a0, a1);
        }
        __syncthreads();
    }
    if (grp < 36) {
        float v0[9], v1[9]; unpack9(a0, v0); unpack9(a1, v1);
        float bb0 = b_s[tx], bb1 = b_s[tx + 32];
        float* o0 = out + ((size_t)b * 64 + tx) * 108;
        float* o1 = out + ((size_t)b * 64 + tx + 32) * 108;
#pragma unroll
        for (int p = 0; p < 3; p++) {
            int po = grp * 3 + p;
            o0[po] = fmaxf(fmaxf(fmaxf(v0[3 * p], v0[3 * p + 1]), v0[3 * p + 2]) + bb0, 0.f);
            o1[po] = fmaxf(fmaxf(fmaxf(v1[3 * p], v1[3 * p + 1]), v1[3 * p + 2]) + bb1, 0.f);
        }
    }
#undef C2_LDG
#undef C2_STS
}

// conv3: [B,64,108] -> conv+relu+pool3 -> mean33 -> [B,128]
// 16 weight tiles (4 ic), double-buffered; 2 blocks/SM.
#define C3_WTILE (32 * 65)
#define CONV3_SMEM ((14080 + 2 * C3_WTILE + 64) * 4)
__global__ void __launch_bounds__(352, 2) conv3_kernel(
        const float* __restrict__ c2, const float* __restrict__ K3,
        const float* __restrict__ cb3, float* __restrict__ c3) {
    extern __shared__ __align__(16) float sm3[];
    float* inA = sm3;                  // 64*11*20
    float* w2 = sm3 + 14080;           // 2 x (32 x 65)
    float* b_s = w2 + 2 * C3_WTILE;
    int b = blockIdx.x;
    int ocz = blockIdx.y;              // 0,1 -> oc base 0,64
    int tx = threadIdx.x, ty = threadIdx.y;
    int tid = ty * 32 + tx;            // 352 threads
    for (int i = tid; i < 14080; i += 352) {
        int ic = i / 220, r = i % 220, t = r / 20, j = r % 20;
        int l = t * 9 + j;
        inA[i] = (l < 108) ? c2[(size_t)b * 6912 + ic * 108 + l] : 0.f;
    }
    if (tid < 64) b_s[tid] = cb3[ocz * 64 + tid];

    // weight pipeline: 6 guarded slots/thread (2048/352)
    float v[6];
#define C3_LDG(t) { _Pragma("unroll") for (int u = 0; u < 6; u++) { \
        int i = tid + u * 352; if (i < 2048) { int rr = i & 31, oc = i >> 5; \
        v[u] = K3[((size_t)(ocz * 64 + oc)) * 512 + (t) * 32 + rr]; } } }
#define C3_STS(buf) { _Pragma("unroll") for (int u = 0; u < 6; u++) { \
        int i = tid + u * 352; if (i < 2048) { int rr = i & 31, oc = i >> 5; \
        (buf)[rr * 65 + oc] = v[u]; } } }
    C3_LDG(0); C3_STS(w2); C3_LDG(1);
    __syncthreads();

    ull a0[5] = {}, a1[5] = {};
    for (int t = 0; t < 16; t++) {
        float* cur = w2 + (t & 1) * C3_WTILE;
        if (t + 1 < 16) { C3_STS(w2 + ((t + 1) & 1) * C3_WTILE); }
        if (t + 2 < 16) { C3_LDG(t + 2); }
#pragma unroll
        for (int ic2 = 0; ic2 < 4; ic2++) {
            int ic = t * 4 + ic2;
            ic_upd_2oc(&inA[(ic * 11 + ty) * 20], &cur[ic2 * 8 * 65], tx, a0, a1);
        }
        __syncthreads();
    }
    float v0[9], v1[9]; unpack9(a0, v0); unpack9(a1, v1);
    float bb0 = b_s[tx], bb1 = b_s[tx + 32];
    float s0 = 0.f, s1 = 0.f;
#pragma unroll
    for (int p = 0; p < 3; p++) {
        s0 += fmaxf(fmaxf(fmaxf(v0[3 * p], v0[3 * p + 1]), v0[3 * p + 2]) + bb0, 0.f);
        s1 += fmaxf(fmaxf(fmaxf(v1[3 * p], v1[3 * p + 1]), v1[3 * p + 2]) + bb1, 0.f);
    }
    atomicAdd(&c3[(size_t)b * 128 + ocz * 64 + tx], s0 * (1.0f / 33.0f));
    atomicAdd(&c3[(size_t)b * 128 + ocz * 64 + tx + 32], s1 * (1.0f / 33.0f));
#undef C3_LDG
#undef C3_STS
}

// ------------------------ stream fork/join context --------------------------
struct Ctx {
    cudaStream_t s2 = nullptr;
    cudaEvent_t eF = nullptr, eJ = nullptr;
    bool ok = false;
    Ctx() {
        ok = (cudaStreamCreateWithFlags(&s2, cudaStreamNonBlocking) == cudaSuccess) &&
             (cudaEventCreateWithFlags(&eF, cudaEventDisableTiming) == cudaSuccess) &&
             (cudaEventCreateWithFlags(&eJ, cudaEventDisableTiming) == cudaSuccess);
    }
};
static Ctx g_ctx;

// ------------------------ host orchestration --------------------------------
extern "C" void kernel_launch(void* const* d_in, const int* in_sizes, int n_in,
                              void* d_out, int out_size) {
    const float* x    = (const float*)d_in[0];
    const int*   ei   = (const int*)d_in[1];
    const int*   batch= (const int*)d_in[2];
    const float* tgt  = (const float*)d_in[3];
    const float* W1 = (const float*)d_in[4];   const float* b1 = (const float*)d_in[5];
    const float* W2 = (const float*)d_in[6];   const float* b2 = (const float*)d_in[7];
    const float* W3 = (const float*)d_in[8];   const float* b3 = (const float*)d_in[9];
    const float* Wg1= (const float*)d_in[10];  const float* bg1= (const float*)d_in[11];
    const float* Wg2= (const float*)d_in[12];  const float* bg2= (const float*)d_in[13];
    const float* K1 = (const float*)d_in[14];  const float* cb1= (const float*)d_in[15];
    const float* K2 = (const float*)d_in[16];  const float* cb2= (const float*)d_in[17];
    const float* K3 = (const float*)d_in[18];  const float* cb3= (const float*)d_in[19];
    const float* Wxt= (const float*)d_in[20];  const float* bxt= (const float*)d_in[21];
    const float* Wf1= (const float*)d_in[22];  const float* bf1= (const float*)d_in[23];
    const float* Wf2= (const float*)d_in[24];  const float* bf2= (const float*)d_in[25];
    const float* Wo = (const float*)d_in[26];  const float* bo = (const float*)d_in[27];
    float* out = (float*)d_out;

    float *p_dis, *p_h, *p_feat, *p_agg, *p_pool, *p_t1, *p_xc, *p_c1, *p_c2, *p_c3, *p_f1, *p_f2;
    int* p_deg;
    cudaGetSymbolAddress((void**)&p_dis, g_dis);
    cudaGetSymbolAddress((void**)&p_deg, g_deg);
    cudaGetSymbolAddress((void**)&p_h, g_h);
    cudaGetSymbolAddress((void**)&p_feat, g_feat);
    cudaGetSymbolAddress((void**)&p_agg, g_agg);
    cudaGetSymbolAddress((void**)&p_pool, g_pool);
    cudaGetSymbolAddress((void**)&p_t1, g_t1);
    cudaGetSymbolAddress((void**)&p_xc, g_xc);
    cudaGetSymbolAddress((void**)&p_c1, g_c1);
    cudaGetSymbolAddress((void**)&p_c2, g_c2);
    cudaGetSymbolAddress((void**)&p_c3, g_c3);
    cudaGetSymbolAddress((void**)&p_f1, g_f1);
    cudaGetSymbolAddress((void**)&p_f2, g_f2);

    const int TPB = 256;
    const int gE = (EE + TPB - 1) / TPB;
    const int gN = (NN + TPB - 1) / TPB;

    bool fork = g_ctx.ok;
    cudaStream_t sg = fork ? g_ctx.s2 : (cudaStream_t)0;

    if (fork) {
        cudaEventRecord(g_ctx.eF, 0);
        cudaStreamWaitEvent(sg, g_ctx.eF, 0);
    }

    cudaFuncSetAttribute(conv2_kernel, cudaFuncAttributeMaxDynamicSharedMemorySize, CONV2_SMEM);
    cudaFuncSetAttribute(conv3_kernel, cudaFuncAttributeMaxDynamicSharedMemorySize, CONV3_SMEM);

    // Submission order: conv3 is the 6th launch (ncu -s 5 -c 1 window).
    cudaMemsetAsync(p_deg, 0, NN * sizeof(int), sg);                                 // 1
    deg_kernel<<<gE, TPB, 0, sg>>>(ei, p_deg);                                       // 2
    conv1_kernel<<<dim3(BB, 14), dim3(32, 8)>>>(tgt, K1, cb1, p_c1);                 // 3
    cudaMemsetAsync(p_c3, 0, BB * 128 * sizeof(float));                              // 4
    conv2_kernel<<<dim3(BB, 5), dim3(32, 8), CONV2_SMEM>>>(p_c1, K2, cb2, p_c2);     // 5
    conv3_kernel<<<dim3(BB, 2), dim3(32, 11), CONV3_SMEM>>>(p_c2, K3, cb3, p_c3);    // 6 <- profiled
    gemm_kernel<<<dim3(2, 8), 256>>>(p_c3, Wxt, bxt, p_xc, BB, 128, 128, 256, 128, 1);

    // ---- graph branch (stream sg) ----
    dis_kernel<<<gN, TPB, 0, sg>>>(p_deg, p_dis);
    transform1<<<gN, TPB, 0, sg>>>(x, W1, p_dis, p_h);
    cudaMemsetAsync(p_agg, 0, (size_t)NN * 4 * sizeof(float), sg);
    scatter_kernel<4><<<gE, TPB, 0, sg>>>(ei, p_h, p_agg);
    combine_transform<4, 8><<<gN, TPB, 0, sg>>>(p_agg, p_h, p_dis, b1, W2, p_feat);

    cudaMemsetAsync(p_agg, 0, (size_t)NN * 8 * sizeof(float), sg);
    scatter_kernel<8><<<gE, TPB, 0, sg>>>(ei, p_feat, p_agg);
    combine_transform<8, 16><<<gN, TPB, 0, sg>>>(p_agg, p_feat, p_dis, b2, W3, p_h);

    cudaMemsetAsync(p_agg, 0, (size_t)NN * 16 * sizeof(float), sg);
    scatter_kernel<16><<<gE, TPB, 0, sg>>>(ei, p_h, p_agg);
    cudaMemsetAsync(p_pool, 0, BB * 16 * sizeof(float), sg);
    combine_pool<<<gN, TPB, 0, sg>>>(p_agg, p_h, p_dis, b3, batch, p_pool);

    gemm_kernel<<<dim3(16, 8), 256, 0, sg>>>(p_pool, Wg1, bg1, p_t1, BB, 16, 1024, 1024, 0, 1);
    gemm_kernel<<<dim3(2, 8), 256, 0, sg>>>(p_t1, Wg2, bg2, p_xc, BB, 1024, 128, 256, 0, 0);
    if (fork) cudaEventRecord(g_ctx.eJ, sg);

    // ---- join + fusion head (stream 0) ----
    if (fork) cudaStreamWaitEvent(0, g_ctx.eJ, 0);
    gemm_kernel<<<dim3(16, 8), 256>>>(p_xc, Wf1, bf1, p_f1, BB, 256, 1024, 1024, 0, 1);
    gemm_kernel<<<dim3(8, 8), 256>>>(p_f1, Wf2, bf2, p_f2, BB, 1024, 512, 512, 0, 1);
    gemm_kernel<<<dim3(1, 8), 256>>>(p_f2, Wo, bo, out, BB, 512, 2, 2, 0, 0);
}

// round 9
// speedup vs baseline: 1.2862x; 1.0861x over previous
#include <cuda_runtime.h>
#include <cuda_bf16.h>
#include <cstdint>

#define NN 200000
#define EE 3200000
#define BB 512
#define LL 1000

typedef unsigned long long ull;

// ------------------------ scratch (device globals, no allocs) ---------------
__device__ float g_dis[NN];
__device__ int   g_deg[NN];
__device__ float g_h[NN * 16];
__device__ float g_feat[NN * 16];
__device__ float g_agg[NN * 16];
__device__ float g_pool[BB * 16];
__device__ float g_t1[BB * 1024];
__device__ float g_xc[BB * 256];
__device__ float g_c1[BB * 32 * 331];
__device__ float g_c2[BB * 64 * 108];
__device__ float g_c3[BB * 128];
__device__ float g_f1[BB * 1024];
__device__ float g_f2[BB * 512];

// ------------------------ f32x2 helpers --------------------------------------
__device__ __forceinline__ ull pk2(float lo, float hi) {
    ull r; asm("mov.b64 %0, {%1, %2};" : "=l"(r) : "f"(lo), "f"(hi)); return r;
}
__device__ __forceinline__ float2 upk2(ull v) {
    float2 r; asm("mov.b64 {%0, %1}, %2;" : "=f"(r.x), "=f"(r.y) : "l"(v)); return r;
}
__device__ __forceinline__ void ffma2(ull& d, ull a, ull b) {
    asm("fma.rn.f32x2 %0, %1, %2, %0;" : "+l"(d) : "l"(a), "l"(b));
}

// ------------------------ graph branch --------------------------------------
__global__ void deg_kernel(const int* __restrict__ ei, int* __restrict__ deg) {
    int e = blockIdx.x * blockDim.x + threadIdx.x;
    if (e >= EE) return;
    atomicAdd(&deg[ei[EE + e]], 1);
}

__global__ void dis_kernel(const int* __restrict__ deg, float* __restrict__ dis) {
    int i = blockIdx.x * blockDim.x + threadIdx.x;
    if (i >= NN) return;
    dis[i] = rsqrtf((float)deg[i] + 1.0f);
}

// hs = dis[i] * (x @ W1)
__global__ void transform1(const float* __restrict__ x, const float* __restrict__ W,
                           const float* __restrict__ dis, float* __restrict__ hs) {
    __shared__ float Ws[16];
    int tid = threadIdx.x;
    if (tid < 16) Ws[tid] = W[tid];
    __syncthreads();
    int i = blockIdx.x * blockDim.x + tid;
    if (i >= NN) return;
    float xi[4];
#pragma unroll
    for (int f = 0; f < 4; f++) xi[f] = x[(size_t)i * 4 + f];
    float dd = dis[i];
#pragma unroll
    for (int fo = 0; fo < 4; fo++) {
        float s = 0.f;
#pragma unroll
        for (int fi = 0; fi < 4; fi++) s = fmaf(xi[fi], Ws[fi * 4 + fo], s);
        hs[(size_t)i * 4 + fo] = dd * s;
    }
}

// pure copy-scatter: agg[dst] += hs[src]
template <int F>
__global__ void scatter_kernel(const int* __restrict__ ei, const float* __restrict__ hs,
                               float* __restrict__ agg) {
    int e = blockIdx.x * blockDim.x + threadIdx.x;
    if (e >= EE) return;
    int s = __ldg(&ei[e]);
    int d = __ldg(&ei[EE + e]);
    const float4* p = reinterpret_cast<const float4*>(hs + (size_t)s * F);
    float* ad = agg + (size_t)d * F;
#pragma unroll
    for (int q = 0; q < F / 4; q++) {
        float4 m = p[q];
        asm volatile("red.global.add.v4.f32 [%0], {%1,%2,%3,%4};"
                     :: "l"(ad + q * 4), "f"(m.x), "f"(m.y), "f"(m.z), "f"(m.w)
                     : "memory");
    }
}

// feat = relu(dis*(agg+hs)+b); out = dis * (feat @ W)
template <int F, int FO>
__global__ void combine_transform(const float* __restrict__ agg, const float* __restrict__ hs,
                                  const float* __restrict__ dis, const float* __restrict__ bias,
                                  const float* __restrict__ W, float* __restrict__ out) {
    __shared__ float Ws[F * FO];
    __shared__ float bs[F];
    int tid = threadIdx.x;
    if (tid < F * FO) Ws[tid] = W[tid];
    if (tid < F) bs[tid] = bias[tid];
    __syncthreads();
    int i = blockIdx.x * blockDim.x + tid;
    if (i >= NN) return;
    float dd = dis[i];
    float v[F];
#pragma unroll
    for (int f = 0; f < F; f++)
        v[f] = fmaxf(dd * (agg[(size_t)i * F + f] + hs[(size_t)i * F + f]) + bs[f], 0.f);
#pragma unroll
    for (int fo = 0; fo < FO; fo++) {
        float s = 0.f;
#pragma unroll
        for (int f = 0; f < F; f++) s = fmaf(v[f], Ws[f * FO + fo], s);
        out[(size_t)i * FO + fo] = dd * s;
    }
}

// final GCN layer + batch max pool
__global__ void combine_pool(const float* __restrict__ agg, const float* __restrict__ hs,
                             const float* __restrict__ dis, const float* __restrict__ bias,
                             const int* __restrict__ batch, float* __restrict__ pool) {
    __shared__ float bs[16];
    int tid = threadIdx.x;
    if (tid < 16) bs[tid] = bias[tid];
    __syncthreads();
    int i = blockIdx.x * blockDim.x + tid;
    if (i >= NN) return;
    float dd = dis[i];
    float v[16];
#pragma unroll
    for (int f = 0; f < 16; f++)
        v[f] = fmaxf(dd * (agg[(size_t)i * 16 + f] + hs[(size_t)i * 16 + f]) + bs[f], 0.f);
    int bb = batch[i];
    unsigned m = __activemask();
    bool uni = false;
    if (m == 0xffffffffu) {
        int bb0 = __shfl_sync(0xffffffffu, bb, 0);
        uni = __all_sync(0xffffffffu, bb == bb0);
    }
    int* p = reinterpret_cast<int*>(pool + (size_t)bb * 16);
    if (uni) {
#pragma unroll
        for (int f = 0; f < 16; f++) {
            float t = v[f];
#pragma unroll
            for (int o = 16; o; o >>= 1) t = fmaxf(t, __shfl_xor_sync(0xffffffffu, t, o));
            v[f] = t;
        }
        if ((tid & 31) == 0)
#pragma unroll
            for (int f = 0; f < 16; f++) atomicMax(&p[f], __float_as_int(v[f]));
    } else {
#pragma unroll
        for (int f = 0; f < 16; f++) atomicMax(&p[f], __float_as_int(v[f]));
    }
}

// ------------------------ generic GEMM (f32x2) -------------------------------
__global__ void gemm_kernel(const float* __restrict__ A, const float* __restrict__ W,
                            const float* __restrict__ bias, float* __restrict__ C,
                            int M, int K, int Nc, int ldc, int coloff, int relu) {
    const int BM = 64, BN = 64, BK = 8;
    __shared__ __align__(16) float As[BK][BM];
    __shared__ __align__(16) float Bs[BK][BN];
    int tid = threadIdx.x;
    int tc = tid & 15, tr = tid >> 4;
    int brow = blockIdx.y * BM, bcol = blockIdx.x * BN;
    ull acc[4][2] = {};
    for (int k0 = 0; k0 < K; k0 += BK) {
        for (int i = tid; i < BM * BK; i += 256) {
            int kk = i & 7, m = i >> 3;
            int gr = brow + m, gc = k0 + kk;
            As[kk][m] = (gr < M && gc < K) ? A[(size_t)gr * K + gc] : 0.f;
        }
        for (int i = tid; i < BN * BK; i += 256) {
            int n = i & 63, kk = i >> 6;
            int gc = bcol + n, gr = k0 + kk;
            Bs[kk][n] = (gr < K && gc < Nc) ? W[(size_t)gr * Nc + gc] : 0.f;
        }
        __syncthreads();
#pragma unroll
        for (int kk = 0; kk < BK; kk++) {
            ull b0 = *reinterpret_cast<const ull*>(&Bs[kk][tc * 4]);
            ull b1 = *reinterpret_cast<const ull*>(&Bs[kk][tc * 4 + 2]);
            float4 av = *reinterpret_cast<const float4*>(&As[kk][tr * 4]);
            float aa[4] = {av.x, av.y, av.z, av.w};
#pragma unroll
            for (int u = 0; u < 4; u++) {
                ull a2 = pk2(aa[u], aa[u]);
                ffma2(acc[u][0], b0, a2);
                ffma2(acc[u][1], b1, a2);
            }
        }
        __syncthreads();
    }
#pragma unroll
    for (int u = 0; u < 4; u++) {
        int r = brow + tr * 4 + u;
        if (r >= M) continue;
#pragma unroll
        for (int v2 = 0; v2 < 2; v2++) {
            float2 pv = upk2(acc[u][v2]);
            float vals[2] = {pv.x, pv.y};
#pragma unroll
            for (int w = 0; w < 2; w++) {
                int c = bcol + tc * 4 + v2 * 2 + w;
                if (c >= Nc) continue;
                float val = vals[w] + bias[c];
                if (relu) val = fmaxf(val, 0.f);
                C[(size_t)r * ldc + coloff + c] = val;
            }
        }
    }
}

// ------------------------ conv inner helpers --------------------------------
// xA: 20 contiguous 16B-aligned floats (positions p..p+19, zero padded).
__device__ __forceinline__ void load_e10(const float* __restrict__ xA, ull e[10]) {
    const ulonglong2* pA = reinterpret_cast<const ulonglong2*>(xA);
#pragma unroll
    for (int i = 0; i < 5; i++) {
        ulonglong2 va = pA[i]; e[2 * i] = va.x; e[2 * i + 1] = va.y;
    }
}
__device__ __forceinline__ void make_o8(const ull e[10], ull o[8]) {
#pragma unroll
    for (int j = 0; j < 8; j++)
        o[j] = (e[j] >> 32) | (e[j + 1] << 32);
}

// conv1 path: 1 oc (w stride 33), position-pair accumulators
__device__ __forceinline__ void ic_upd_1oc(const float* __restrict__ xA,
                                           const float* __restrict__ w, ull a0[5]) {
    ull e[10], o[8];
    load_e10(xA, e); make_o8(e, o);
#pragma unroll
    for (int k = 0; k < 8; k++) {
        float wv = w[k * 33];
        ull w2 = pk2(wv, wv);
        const ull* xpp = (k & 1) ? &o[k >> 1] : &e[k >> 1];
#pragma unroll
        for (int j = 0; j < 5; j++) ffma2(a0[j], xpp[j], w2);
    }
}

// conv2/3 path: oc-pair accumulators. acc[p] = (sum_oc_tx, sum_oc_tx+32),
// weights pre-interleaved in smem rows of 66 floats: ws[r*66 + 2*oc' + h].
// Per ic: 5 LDS.128 (x) + 17 pk2 + 8 LDS.64 (w pairs) + 72 FFMA2. No w-pack.
__device__ __forceinline__ void ic_upd_ocpair(const float* __restrict__ xA,
                                              const float* __restrict__ ws, int tx,
                                              ull acc[9]) {
    float4 x0 = *reinterpret_cast<const float4*>(xA);
    float4 x1 = *reinterpret_cast<const float4*>(xA + 4);
    float4 x2 = *reinterpret_cast<const float4*>(xA + 8);
    float4 x3 = *reinterpret_cast<const float4*>(xA + 12);
    float4 x4 = *reinterpret_cast<const float4*>(xA + 16);
    float xs[20] = {x0.x, x0.y, x0.z, x0.w, x1.x, x1.y, x1.z, x1.w,
                    x2.x, x2.y, x2.z, x2.w, x3.x, x3.y, x3.z, x3.w,
                    x4.x, x4.y, x4.z, x4.w};
    ull xd[17];
#pragma unroll
    for (int i = 0; i < 17; i++) xd[i] = pk2(xs[i], xs[i]);
#pragma unroll
    for (int k = 0; k < 8; k++) {
        ull wp = *reinterpret_cast<const ull*>(ws + k * 66 + 2 * tx);
#pragma unroll
        for (int p = 0; p < 9; p++) ffma2(acc[p], xd[p + k], wp);
    }
}

__device__ __forceinline__ void unpack9(const ull acc[5], float a[9]) {
#pragma unroll
    for (int j = 0; j < 4; j++) {
        float2 t = upk2(acc[j]);
        a[2 * j] = t.x; a[2 * j + 1] = t.y;
    }
    a[8] = upk2(acc[4]).x;
}

// conv1: target [B,L,5] -> conv(k=8)+relu+maxpool3 -> [B,32,331]
__global__ void conv1_kernel(const float* __restrict__ tgt, const float* __restrict__ K1,
                             const float* __restrict__ cb1, float* __restrict__ out) {
    __shared__ __align__(16) float inA[5 * 8 * 20];
    __shared__ float w_s[40 * 33];
    __shared__ float b_s[32];
    int b = blockIdx.x;
    int g0 = blockIdx.y * 8;
    int tx = threadIdx.x, ty = threadIdx.y;
    int tid = ty * 32 + tx;
    int L0 = g0 * 9;
    for (int i = tid; i < 800; i += 256) {
        int c = i / 160, r = i % 160, t = r / 20, j = r % 20;
        int l = L0 + t * 9 + j;
        inA[i] = (l < LL) ? tgt[(size_t)b * (LL * 5) + l * 5 + c] : 0.f;
    }
    for (int i = tid; i < 2048; i += 256) {
        int oc = i >> 6, r = i & 63;
        if (r < 40) w_s[r * 33 + oc] = K1[oc * 40 + r];
    }
    if (tid < 32) b_s[tid] = cb1[tid];
    __syncthreads();

    ull acc[5] = {};
#pragma unroll
    for (int ic = 0; ic < 5; ic++)
        ic_upd_1oc(&inA[(ic * 8 + ty) * 20], &w_s[ic * 8 * 33 + tx], acc);
    float a[9]; unpack9(acc, a);
    float bb = b_s[tx];
    int grp = g0 + ty;
#pragma unroll
    for (int p = 0; p < 3; p++) {
        int po = grp * 3 + p;
        if (po < 331) {
            float v = fmaxf(fmaxf(a[3 * p], a[3 * p + 1]), a[3 * p + 2]) + bb;
            out[((size_t)b * 32 + tx) * 331 + po] = fmaxf(v, 0.f);
        }
    }
}

// conv2: [B,32,331] -> conv(k=8)+relu+pool3 -> [B,64,108]
// 8 weight tiles (4 ic), interleaved oc-pairs, double-buffered.
#define C2_WTILE (32 * 66)
#define CONV2_SMEM ((5120 + 2 * C2_WTILE + 64) * 4)
__global__ void conv2_kernel(const float* __restrict__ c1, const float* __restrict__ K2,
                             const float* __restrict__ cb2, float* __restrict__ out) {
    extern __shared__ __align__(16) float sm2[];
    float* inA = sm2;                 // 32*8*20
    float* w2 = sm2 + 5120;           // 2 x (32 x 66), [r][2*oc'+h]
    float* b_s = w2 + 2 * C2_WTILE;
    int b = blockIdx.x;
    int g0 = blockIdx.y * 8;
    int tx = threadIdx.x, ty = threadIdx.y;
    int tid = ty * 32 + tx;
    int L0 = g0 * 9;
    for (int i = tid; i < 5120; i += 256) {
        int ic = i / 160, r = i % 160, t = r / 20, j = r % 20;
        int l = L0 + t * 9 + j;
        inA[i] = (l < 331) ? c1[((size_t)b * 32 + ic) * 331 + l] : 0.f;
    }
    if (tid < 64) b_s[tid] = cb2[tid];

    // weight pipeline: 8 slots/thread; slot u covers oc = oc8 + 8u
    float v[8];
    int rr = tid & 31, oc8 = tid >> 5;
#define C2_LDG(t) { _Pragma("unroll") for (int u = 0; u < 8; u++) \
        v[u] = K2[(size_t)(oc8 + 8 * u) * 256 + (t) * 32 + rr]; }
#define C2_STS(buf) { _Pragma("unroll") for (int u = 0; u < 8; u++) { \
        int oc = oc8 + 8 * u; \
        (buf)[rr * 66 + 2 * (oc & 31) + (oc >> 5)] = v[u]; } }
    C2_LDG(0); C2_STS(w2); C2_LDG(1);
    __syncthreads();

    int grp = g0 + ty;
    ull acc[9] = {};
    for (int t = 0; t < 8; t++) {
        float* cur = w2 + (t & 1) * C2_WTILE;
        if (t + 1 < 8) { C2_STS(w2 + ((t + 1) & 1) * C2_WTILE); }
        if (t + 2 < 8) { C2_LDG(t + 2); }
#pragma unroll
        for (int ic2 = 0; ic2 < 4; ic2++) {
            int ic = t * 4 + ic2;
            ic_upd_ocpair(&inA[(ic * 8 + ty) * 20], &cur[ic2 * 8 * 66], tx, acc);
        }
        __syncthreads();
    }
    if (grp < 36) {
        float v0[9], v1[9];
#pragma unroll
        for (int p = 0; p < 9; p++) {
            float2 pv = upk2(acc[p]); v0[p] = pv.x; v1[p] = pv.y;
        }
        float bb0 = b_s[tx], bb1 = b_s[tx + 32];
        float* o0 = out + ((size_t)b * 64 + tx) * 108;
        float* o1 = out + ((size_t)b * 64 + tx + 32) * 108;
#pragma unroll
        for (int p = 0; p < 3; p++) {
            int po = grp * 3 + p;
            o0[po] = fmaxf(fmaxf(fmaxf(v0[3 * p], v0[3 * p + 1]), v0[3 * p + 2]) + bb0, 0.f);
            o1[po] = fmaxf(fmaxf(fmaxf(v1[3 * p], v1[3 * p + 1]), v1[3 * p + 2]) + bb1, 0.f);
        }
    }
#undef C2_LDG
#undef C2_STS
}

// conv3: [B,64,108] -> conv+relu+pool3 -> mean33 -> [B,128]
// 16 weight tiles (4 ic), interleaved oc-pairs, double-buffered; 2 blocks/SM.
#define C3_WTILE (32 * 66)
#define CONV3_SMEM ((14080 + 2 * C3_WTILE + 64) * 4)
__global__ void __launch_bounds__(352, 2) conv3_kernel(
        const float* __restrict__ c2, const float* __restrict__ K3,
        const float* __restrict__ cb3, float* __restrict__ c3) {
    extern __shared__ __align__(16) float sm3[];
    float* inA = sm3;                  // 64*11*20
    float* w2 = sm3 + 14080;           // 2 x (32 x 66)
    float* b_s = w2 + 2 * C3_WTILE;
    int b = blockIdx.x;
    int ocz = blockIdx.y;              // 0,1 -> oc base 0,64
    int tx = threadIdx.x, ty = threadIdx.y;
    int tid = ty * 32 + tx;            // 352 threads
    for (int i = tid; i < 14080; i += 352) {
        int ic = i / 220, r = i % 220, t = r / 20, j = r % 20;
        int l = t * 9 + j;
        inA[i] = (l < 108) ? c2[(size_t)b * 6912 + ic * 108 + l] : 0.f;
    }
    if (tid < 64) b_s[tid] = cb3[ocz * 64 + tid];

    // weight pipeline: 6 guarded slots/thread (2048/352)
    float v[6];
#define C3_LDG(t) { _Pragma("unroll") for (int u = 0; u < 6; u++) { \
        int i = tid + u * 352; if (i < 2048) { int rr = i & 31, oc = i >> 5; \
        v[u] = K3[((size_t)(ocz * 64 + oc)) * 512 + (t) * 32 + rr]; } } }
#define C3_STS(buf) { _Pragma("unroll") for (int u = 0; u < 6; u++) { \
        int i = tid + u * 352; if (i < 2048) { int rr = i & 31, oc = i >> 5; \
        (buf)[rr * 66 + 2 * (oc & 31) + (oc >> 5)] = v[u]; } } }
    C3_LDG(0); C3_STS(w2); C3_LDG(1);
    __syncthreads();

    ull acc[9] = {};
    for (int t = 0; t < 16; t++) {
        float* cur = w2 + (t & 1) * C3_WTILE;
        if (t + 1 < 16) { C3_STS(w2 + ((t + 1) & 1) * C3_WTILE); }
        if (t + 2 < 16) { C3_LDG(t + 2); }
#pragma unroll
        for (int ic2 = 0; ic2 < 4; ic2++) {
            int ic = t * 4 + ic2;
            ic_upd_ocpair(&inA[(ic * 11 + ty) * 20], &cur[ic2 * 8 * 66], tx, acc);
        }
        __syncthreads();
    }
    float v0[9], v1[9];
#pragma unroll
    for (int p = 0; p < 9; p++) {
        float2 pv = upk2(acc[p]); v0[p] = pv.x; v1[p] = pv.y;
    }
    float bb0 = b_s[tx], bb1 = b_s[tx + 32];
    float s0 = 0.f, s1 = 0.f;
#pragma unroll
    for (int p = 0; p < 3; p++) {
        s0 += fmaxf(fmaxf(fmaxf(v0[3 * p], v0[3 * p + 1]), v0[3 * p + 2]) + bb0, 0.f);
        s1 += fmaxf(fmaxf(fmaxf(v1[3 * p], v1[3 * p + 1]), v1[3 * p + 2]) + bb1, 0.f);
    }
    atomicAdd(&c3[(size_t)b * 128 + ocz * 64 + tx], s0 * (1.0f / 33.0f));
    atomicAdd(&c3[(size_t)b * 128 + ocz * 64 + tx + 32], s1 * (1.0f / 33.0f));
#undef C3_LDG
#undef C3_STS
}

// ------------------------ stream fork/join context --------------------------
struct Ctx {
    cudaStream_t s2 = nullptr;
    cudaEvent_t eF = nullptr, eJ = nullptr;
    bool ok = false;
    Ctx() {
        ok = (cudaStreamCreateWithFlags(&s2, cudaStreamNonBlocking) == cudaSuccess) &&
             (cudaEventCreateWithFlags(&eF, cudaEventDisableTiming) == cudaSuccess) &&
             (cudaEventCreateWithFlags(&eJ, cudaEventDisableTiming) == cudaSuccess);
    }
};
static Ctx g_ctx;

// ------------------------ host orchestration --------------------------------
extern "C" void kernel_launch(void* const* d_in, const int* in_sizes, int n_in,
                              void* d_out, int out_size) {
    const float* x    = (const float*)d_in[0];
    const int*   ei   = (const int*)d_in[1];
    const int*   batch= (const int*)d_in[2];
    const float* tgt  = (const float*)d_in[3];
    const float* W1 = (const float*)d_in[4];   const float* b1 = (const float*)d_in[5];
    const float* W2 = (const float*)d_in[6];   const float* b2 = (const float*)d_in[7];
    const float* W3 = (const float*)d_in[8];   const float* b3 = (const float*)d_in[9];
    const float* Wg1= (const float*)d_in[10];  const float* bg1= (const float*)d_in[11];
    const float* Wg2= (const float*)d_in[12];  const float* bg2= (const float*)d_in[13];
    const float* K1 = (const float*)d_in[14];  const float* cb1= (const float*)d_in[15];
    const float* K2 = (const float*)d_in[16];  const float* cb2= (const float*)d_in[17];
    const float* K3 = (const float*)d_in[18];  const float* cb3= (const float*)d_in[19];
    const float* Wxt= (const float*)d_in[20];  const float* bxt= (const float*)d_in[21];
    const float* Wf1= (const float*)d_in[22];  const float* bf1= (const float*)d_in[23];
    const float* Wf2= (const float*)d_in[24];  const float* bf2= (const float*)d_in[25];
    const float* Wo = (const float*)d_in[26];  const float* bo = (const float*)d_in[27];
    float* out = (float*)d_out;

    float *p_dis, *p_h, *p_feat, *p_agg, *p_pool, *p_t1, *p_xc, *p_c1, *p_c2, *p_c3, *p_f1, *p_f2;
    int* p_deg;
    cudaGetSymbolAddress((void**)&p_dis, g_dis);
    cudaGetSymbolAddress((void**)&p_deg, g_deg);
    cudaGetSymbolAddress((void**)&p_h, g_h);
    cudaGetSymbolAddress((void**)&p_feat, g_feat);
    cudaGetSymbolAddress((void**)&p_agg, g_agg);
    cudaGetSymbolAddress((void**)&p_pool, g_pool);
    cudaGetSymbolAddress((void**)&p_t1, g_t1);
    cudaGetSymbolAddress((void**)&p_xc, g_xc);
    cudaGetSymbolAddress((void**)&p_c1, g_c1);
    cudaGetSymbolAddress((void**)&p_c2, g_c2);
    cudaGetSymbolAddress((void**)&p_c3, g_c3);
    cudaGetSymbolAddress((void**)&p_f1, g_f1);
    cudaGetSymbolAddress((void**)&p_f2, g_f2);

    const int TPB = 256;
    const int gE = (EE + TPB - 1) / TPB;
    const int gN = (NN + TPB - 1) / TPB;

    bool fork = g_ctx.ok;
    cudaStream_t sg = fork ? g_ctx.s2 : (cudaStream_t)0;

    if (fork) {
        cudaEventRecord(g_ctx.eF, 0);
        cudaStreamWaitEvent(sg, g_ctx.eF, 0);
    }

    cudaFuncSetAttribute(conv2_kernel, cudaFuncAttributeMaxDynamicSharedMemorySize, CONV2_SMEM);
    cudaFuncSetAttribute(conv3_kernel, cudaFuncAttributeMaxDynamicSharedMemorySize, CONV3_SMEM);

    // Submission order: conv3 is the 6th launch (ncu -s 5 -c 1 window).
    cudaMemsetAsync(p_deg, 0, NN * sizeof(int), sg);                                 // 1
    deg_kernel<<<gE, TPB, 0, sg>>>(ei, p_deg);                                       // 2
    conv1_kernel<<<dim3(BB, 14), dim3(32, 8)>>>(tgt, K1, cb1, p_c1);                 // 3
    cudaMemsetAsync(p_c3, 0, BB * 128 * sizeof(float));                              // 4
    conv2_kernel<<<dim3(BB, 5), dim3(32, 8), CONV2_SMEM>>>(p_c1, K2, cb2, p_c2);     // 5
    conv3_kernel<<<dim3(BB, 2), dim3(32, 11), CONV3_SMEM>>>(p_c2, K3, cb3, p_c3);    // 6 <- profiled
    gemm_kernel<<<dim3(2, 8), 256>>>(p_c3, Wxt, bxt, p_xc, BB, 128, 128, 256, 128, 1);

    // ---- graph branch (stream sg) ----
    dis_kernel<<<gN, TPB, 0, sg>>>(p_deg, p_dis);
    transform1<<<gN, TPB, 0, sg>>>(x, W1, p_dis, p_h);
    cudaMemsetAsync(p_agg, 0, (size_t)NN * 4 * sizeof(float), sg);
    scatter_kernel<4><<<gE, TPB, 0, sg>>>(ei, p_h, p_agg);
    combine_transform<4, 8><<<gN, TPB, 0, sg>>>(p_agg, p_h, p_dis, b1, W2, p_feat);

    cudaMemsetAsync(p_agg, 0, (size_t)NN * 8 * sizeof(float), sg);
    scatter_kernel<8><<<gE, TPB, 0, sg>>>(ei, p_feat, p_agg);
    combine_transform<8, 16><<<gN, TPB, 0, sg>>>(p_agg, p_feat, p_dis, b2, W3, p_h);

    cudaMemsetAsync(p_agg, 0, (size_t)NN * 16 * sizeof(float), sg);
    scatter_kernel<16><<<gE, TPB, 0, sg>>>(ei, p_h, p_agg);
    cudaMemsetAsync(p_pool, 0, BB * 16 * sizeof(float), sg);
    combine_pool<<<gN, TPB, 0, sg>>>(p_agg, p_h, p_dis, b3, batch, p_pool);

    gemm_kernel<<<dim3(16, 8), 256, 0, sg>>>(p_pool, Wg1, bg1, p_t1, BB, 16, 1024, 1024, 0, 1);
    gemm_kernel<<<dim3(2, 8), 256, 0, sg>>>(p_t1, Wg2, bg2, p_xc, BB, 1024, 128, 256, 0, 0);
    if (fork) cudaEventRecord(g_ctx.eJ, sg);

    // ---- join + fusion head (stream 0) ----
    if (fork) cudaStreamWaitEvent(0, g_ctx.eJ, 0);
    gemm_kernel<<<dim3(16, 8), 256>>>(p_xc, Wf1, bf1, p_f1, BB, 256, 1024, 1024, 0, 1);
    gemm_kernel<<<dim3(8, 8), 256>>>(p_f1, Wf2, bf2, p_f2, BB, 1024, 512, 512, 0, 1);
    gemm_kernel<<<dim3(1, 8), 256>>>(p_f2, Wo, bo, out, BB, 512, 2, 2, 0, 0);
}

// round 10
// speedup vs baseline: 1.3302x; 1.0342x over previous
#include <cuda_runtime.h>
#include <cuda_bf16.h>
#include <cstdint>

#define NN 200000
#define EE 3200000
#define BB 512
#define LL 1000

typedef unsigned long long ull;
typedef unsigned int uint;

// ------------------------ scratch (device globals, no allocs) ---------------
__device__ float g_dis[NN];
__device__ int   g_deg[NN];
__device__ float g_h[NN * 16];
__device__ float g_feat[NN * 16];
__device__ float g_agg[NN * 16];
__device__ float g_pool[BB * 16];
__device__ float g_t1[BB * 1024];
__device__ float g_xc[BB * 256];
__device__ float g_c1[BB * 32 * 331];
__device__ float g_c2[BB * 64 * 108];
__device__ float g_c3[BB * 128];
__device__ float g_f1[BB * 1024];
__device__ float g_f2[BB * 512];

// ------------------------ f32x2 helpers --------------------------------------
__device__ __forceinline__ ull pk2(float lo, float hi) {
    ull r; asm("mov.b64 %0, {%1, %2};" : "=l"(r) : "f"(lo), "f"(hi)); return r;
}
__device__ __forceinline__ float2 upk2(ull v) {
    float2 r; asm("mov.b64 {%0, %1}, %2;" : "=f"(r.x), "=f"(r.y) : "l"(v)); return r;
}
__device__ __forceinline__ void ffma2(ull& d, ull a, ull b) {
    asm("fma.rn.f32x2 %0, %1, %2, %0;" : "+l"(d) : "l"(a), "l"(b));
}

// ------------------------ tf32 helpers ---------------------------------------
__device__ __forceinline__ float tf32_hi(float v) {
    uint u; asm("cvt.rna.tf32.f32 %0, %1;" : "=r"(u) : "f"(v));
    return __uint_as_float(u);
}
__device__ __forceinline__ void mma_tf32(float d[4], uint a0, uint a1, uint a2, uint a3,
                                         uint b0, uint b1) {
    asm volatile("mma.sync.aligned.m16n8k8.row.col.f32.tf32.tf32.f32 "
                 "{%0,%1,%2,%3}, {%4,%5,%6,%7}, {%8,%9}, {%0,%1,%2,%3};"
                 : "+f"(d[0]), "+f"(d[1]), "+f"(d[2]), "+f"(d[3])
                 : "r"(a0), "r"(a1), "r"(a2), "r"(a3), "r"(b0), "r"(b1));
}

// ------------------------ graph branch --------------------------------------
__global__ void deg_kernel(const int* __restrict__ ei, int* __restrict__ deg) {
    int e = blockIdx.x * blockDim.x + threadIdx.x;
    if (e >= EE) return;
    atomicAdd(&deg[ei[EE + e]], 1);
}

__global__ void dis_kernel(const int* __restrict__ deg, float* __restrict__ dis) {
    int i = blockIdx.x * blockDim.x + threadIdx.x;
    if (i >= NN) return;
    dis[i] = rsqrtf((float)deg[i] + 1.0f);
}

__global__ void transform1(const float* __restrict__ x, const float* __restrict__ W,
                           const float* __restrict__ dis, float* __restrict__ hs) {
    __shared__ float Ws[16];
    int tid = threadIdx.x;
    if (tid < 16) Ws[tid] = W[tid];
    __syncthreads();
    int i = blockIdx.x * blockDim.x + tid;
    if (i >= NN) return;
    float xi[4];
#pragma unroll
    for (int f = 0; f < 4; f++) xi[f] = x[(size_t)i * 4 + f];
    float dd = dis[i];
#pragma unroll
    for (int fo = 0; fo < 4; fo++) {
        float s = 0.f;
#pragma unroll
        for (int fi = 0; fi < 4; fi++) s = fmaf(xi[fi], Ws[fi * 4 + fo], s);
        hs[(size_t)i * 4 + fo] = dd * s;
    }
}

template <int F>
__global__ void scatter_kernel(const int* __restrict__ ei, const float* __restrict__ hs,
                               float* __restrict__ agg) {
    int e = blockIdx.x * blockDim.x + threadIdx.x;
    if (e >= EE) return;
    int s = __ldg(&ei[e]);
    int d = __ldg(&ei[EE + e]);
    const float4* p = reinterpret_cast<const float4*>(hs + (size_t)s * F);
    float* ad = agg + (size_t)d * F;
#pragma unroll
    for (int q = 0; q < F / 4; q++) {
        float4 m = p[q];
        asm volatile("red.global.add.v4.f32 [%0], {%1,%2,%3,%4};"
                     :: "l"(ad + q * 4), "f"(m.x), "f"(m.y), "f"(m.z), "f"(m.w)
                     : "memory");
    }
}

template <int F, int FO>
__global__ void combine_transform(const float* __restrict__ agg, const float* __restrict__ hs,
                                  const float* __restrict__ dis, const float* __restrict__ bias,
                                  const float* __restrict__ W, float* __restrict__ out) {
    __shared__ float Ws[F * FO];
    __shared__ float bs[F];
    int tid = threadIdx.x;
    if (tid < F * FO) Ws[tid] = W[tid];
    if (tid < F) bs[tid] = bias[tid];
    __syncthreads();
    int i = blockIdx.x * blockDim.x + tid;
    if (i >= NN) return;
    float dd = dis[i];
    float v[F];
#pragma unroll
    for (int f = 0; f < F; f++)
        v[f] = fmaxf(dd * (agg[(size_t)i * F + f] + hs[(size_t)i * F + f]) + bs[f], 0.f);
#pragma unroll
    for (int fo = 0; fo < FO; fo++) {
        float s = 0.f;
#pragma unroll
        for (int f = 0; f < F; f++) s = fmaf(v[f], Ws[f * FO + fo], s);
        out[(size_t)i * FO + fo] = dd * s;
    }
}

__global__ void combine_pool(const float* __restrict__ agg, const float* __restrict__ hs,
                             const float* __restrict__ dis, const float* __restrict__ bias,
                             const int* __restrict__ batch, float* __restrict__ pool) {
    __shared__ float bs[16];
    int tid = threadIdx.x;
    if (tid < 16) bs[tid] = bias[tid];
    __syncthreads();
    int i = blockIdx.x * blockDim.x + tid;
    if (i >= NN) return;
    float dd = dis[i];
    float v[16];
#pragma unroll
    for (int f = 0; f < 16; f++)
        v[f] = fmaxf(dd * (agg[(size_t)i * 16 + f] + hs[(size_t)i * 16 + f]) + bs[f], 0.f);
    int bb = batch[i];
    unsigned m = __activemask();
    bool uni = false;
    if (m == 0xffffffffu) {
        int bb0 = __shfl_sync(0xffffffffu, bb, 0);
        uni = __all_sync(0xffffffffu, bb == bb0);
    }
    int* p = reinterpret_cast<int*>(pool + (size_t)bb * 16);
    if (uni) {
#pragma unroll
        for (int f = 0; f < 16; f++) {
            float t = v[f];
#pragma unroll
            for (int o = 16; o; o >>= 1) t = fmaxf(t, __shfl_xor_sync(0xffffffffu, t, o));
            v[f] = t;
        }
        if ((tid & 31) == 0)
#pragma unroll
            for (int f = 0; f < 16; f++) atomicMax(&p[f], __float_as_int(v[f]));
    } else {
#pragma unroll
        for (int f = 0; f < 16; f++) atomicMax(&p[f], __float_as_int(v[f]));
    }
}

// ------------------------ generic GEMM (f32x2) -------------------------------
__global__ void gemm_kernel(const float* __restrict__ A, const float* __restrict__ W,
                            const float* __restrict__ bias, float* __restrict__ C,
                            int M, int K, int Nc, int ldc, int coloff, int relu) {
    const int BM = 64, BN = 64, BK = 8;
    __shared__ __align__(16) float As[BK][BM];
    __shared__ __align__(16) float Bs[BK][BN];
    int tid = threadIdx.x;
    int tc = tid & 15, tr = tid >> 4;
    int brow = blockIdx.y * BM, bcol = blockIdx.x * BN;
    ull acc[4][2] = {};
    for (int k0 = 0; k0 < K; k0 += BK) {
        for (int i = tid; i < BM * BK; i += 256) {
            int kk = i & 7, m = i >> 3;
            int gr = brow + m, gc = k0 + kk;
            As[kk][m] = (gr < M && gc < K) ? A[(size_t)gr * K + gc] : 0.f;
        }
        for (int i = tid; i < BN * BK; i += 256) {
            int n = i & 63, kk = i >> 6;
            int gc = bcol + n, gr = k0 + kk;
            Bs[kk][n] = (gr < K && gc < Nc) ? W[(size_t)gr * Nc + gc] : 0.f;
        }
        __syncthreads();
#pragma unroll
        for (int kk = 0; kk < BK; kk++) {
            ull b0 = *reinterpret_cast<const ull*>(&Bs[kk][tc * 4]);
            ull b1 = *reinterpret_cast<const ull*>(&Bs[kk][tc * 4 + 2]);
            float4 av = *reinterpret_cast<const float4*>(&As[kk][tr * 4]);
            float aa[4] = {av.x, av.y, av.z, av.w};
#pragma unroll
            for (int u = 0; u < 4; u++) {
                ull a2 = pk2(aa[u], aa[u]);
                ffma2(acc[u][0], b0, a2);
                ffma2(acc[u][1], b1, a2);
            }
        }
        __syncthreads();
    }
#pragma unroll
    for (int u = 0; u < 4; u++) {
        int r = brow + tr * 4 + u;
        if (r >= M) continue;
#pragma unroll
        for (int v2 = 0; v2 < 2; v2++) {
            float2 pv = upk2(acc[u][v2]);
            float vals[2] = {pv.x, pv.y};
#pragma unroll
            for (int w = 0; w < 2; w++) {
                int c = bcol + tc * 4 + v2 * 2 + w;
                if (c >= Nc) continue;
                float val = vals[w] + bias[c];
                if (relu) val = fmaxf(val, 0.f);
                C[(size_t)r * ldc + coloff + c] = val;
            }
        }
    }
}

// ------------------------ conv1/conv2 scalar helpers -------------------------
__device__ __forceinline__ void load_e10(const float* __restrict__ xA, ull e[10]) {
    const ulonglong2* pA = reinterpret_cast<const ulonglong2*>(xA);
#pragma unroll
    for (int i = 0; i < 5; i++) {
        ulonglong2 va = pA[i]; e[2 * i] = va.x; e[2 * i + 1] = va.y;
    }
}
__device__ __forceinline__ void make_o8(const ull e[10], ull o[8]) {
#pragma unroll
    for (int j = 0; j < 8; j++)
        o[j] = (e[j] >> 32) | (e[j + 1] << 32);
}

__device__ __forceinline__ void ic_upd_1oc(const float* __restrict__ xA,
                                           const float* __restrict__ w, ull a0[5]) {
    ull e[10], o[8];
    load_e10(xA, e); make_o8(e, o);
#pragma unroll
    for (int k = 0; k < 8; k++) {
        float wv = w[k * 33];
        ull w2 = pk2(wv, wv);
        const ull* xpp = (k & 1) ? &o[k >> 1] : &e[k >> 1];
#pragma unroll
        for (int j = 0; j < 5; j++) ffma2(a0[j], xpp[j], w2);
    }
}

// oc-pair accumulators, 16-float x rows (exact k+p span)
__device__ __forceinline__ void ic_upd_ocpair(const float* __restrict__ xA,
                                              const float* __restrict__ ws, int tx,
                                              ull acc[9]) {
    float4 x0 = *reinterpret_cast<const float4*>(xA);
    float4 x1 = *reinterpret_cast<const float4*>(xA + 4);
    float4 x2 = *reinterpret_cast<const float4*>(xA + 8);
    float4 x3 = *reinterpret_cast<const float4*>(xA + 12);
    float xs[16] = {x0.x, x0.y, x0.z, x0.w, x1.x, x1.y, x1.z, x1.w,
                    x2.x, x2.y, x2.z, x2.w, x3.x, x3.y, x3.z, x3.w};
    ull xd[16];
#pragma unroll
    for (int i = 0; i < 16; i++) xd[i] = pk2(xs[i], xs[i]);
#pragma unroll
    for (int k = 0; k < 8; k++) {
        ull wp = *reinterpret_cast<const ull*>(ws + k * 66 + 2 * tx);
#pragma unroll
        for (int p = 0; p < 9; p++) ffma2(acc[p], xd[p + k], wp);
    }
}

__device__ __forceinline__ void unpack9(const ull acc[5], float a[9]) {
#pragma unroll
    for (int j = 0; j < 4; j++) {
        float2 t = upk2(acc[j]);
        a[2 * j] = t.x; a[2 * j + 1] = t.y;
    }
    a[8] = upk2(acc[4]).x;
}

// conv1: target [B,L,5] -> conv(k=8)+relu+maxpool3 -> [B,32,331]
__global__ void conv1_kernel(const float* __restrict__ tgt, const float* __restrict__ K1,
                             const float* __restrict__ cb1, float* __restrict__ out) {
    __shared__ __align__(16) float inA[5 * 8 * 20];
    __shared__ float w_s[40 * 33];
    __shared__ float b_s[32];
    int b = blockIdx.x;
    int g0 = blockIdx.y * 8;
    int tx = threadIdx.x, ty = threadIdx.y;
    int tid = ty * 32 + tx;
    int L0 = g0 * 9;
    for (int i = tid; i < 800; i += 256) {
        int c = i / 160, r = i % 160, t = r / 20, j = r % 20;
        int l = L0 + t * 9 + j;
        inA[i] = (l < LL) ? tgt[(size_t)b * (LL * 5) + l * 5 + c] : 0.f;
    }
    for (int i = tid; i < 2048; i += 256) {
        int oc = i >> 6, r = i & 63;
        if (r < 40) w_s[r * 33 + oc] = K1[oc * 40 + r];
    }
    if (tid < 32) b_s[tid] = cb1[tid];
    __syncthreads();

    ull acc[5] = {};
#pragma unroll
    for (int ic = 0; ic < 5; ic++)
        ic_upd_1oc(&inA[(ic * 8 + ty) * 20], &w_s[ic * 8 * 33 + tx], acc);
    float a[9]; unpack9(acc, a);
    float bb = b_s[tx];
    int grp = g0 + ty;
#pragma unroll
    for (int p = 0; p < 3; p++) {
        int po = grp * 3 + p;
        if (po < 331) {
            float v = fmaxf(fmaxf(a[3 * p], a[3 * p + 1]), a[3 * p + 2]) + bb;
            out[((size_t)b * 32 + tx) * 331 + po] = fmaxf(v, 0.f);
        }
    }
}

// conv2: [B,32,331] -> conv(k=8)+relu+pool3 -> [B,64,108] (scalar f32x2 path)
#define C2_WTILE (32 * 66)
#define CONV2_SMEM ((4096 + 2 * C2_WTILE + 64) * 4)
__global__ void conv2_kernel(const float* __restrict__ c1, const float* __restrict__ K2,
                             const float* __restrict__ cb2, float* __restrict__ out) {
    extern __shared__ __align__(16) float sm2[];
    float* inA = sm2;                 // 32*8*16
    float* w2 = sm2 + 4096;           // 2 x (32 x 66)
    float* b_s = w2 + 2 * C2_WTILE;
    int b = blockIdx.x;
    int g0 = blockIdx.y * 8;
    int tx = threadIdx.x, ty = threadIdx.y;
    int tid = ty * 32 + tx;
    int L0 = g0 * 9;
    for (int i = tid; i < 4096; i += 256) {
        int ic = i >> 7, t = (i >> 4) & 7, j = i & 15;
        int l = L0 + t * 9 + j;
        inA[i] = (l < 331) ? c1[((size_t)b * 32 + ic) * 331 + l] : 0.f;
    }
    if (tid < 64) b_s[tid] = cb2[tid];

    float v[8];
    int rr = tid & 31, oc8 = tid >> 5;
#define C2_LDG(t) { _Pragma("unroll") for (int u = 0; u < 8; u++) \
        v[u] = K2[(size_t)(oc8 + 8 * u) * 256 + (t) * 32 + rr]; }
#define C2_STS(buf) { _Pragma("unroll") for (int u = 0; u < 8; u++) { \
        int oc = oc8 + 8 * u; \
        (buf)[rr * 66 + 2 * (oc & 31) + (oc >> 5)] = v[u]; } }
    C2_LDG(0); C2_STS(w2); C2_LDG(1);
    __syncthreads();

    int grp = g0 + ty;
    ull acc[9] = {};
    for (int t = 0; t < 8; t++) {
        float* cur = w2 + (t & 1) * C2_WTILE;
        if (t + 1 < 8) { C2_STS(w2 + ((t + 1) & 1) * C2_WTILE); }
        if (t + 2 < 8) { C2_LDG(t + 2); }
#pragma unroll
        for (int ic2 = 0; ic2 < 4; ic2++) {
            int ic = t * 4 + ic2;
            ic_upd_ocpair(&inA[(ic * 8 + ty) * 16], &cur[ic2 * 8 * 66], tx, acc);
        }
        __syncthreads();
    }
    if (grp < 36) {
        float v0[9], v1[9];
#pragma unroll
        for (int p = 0; p < 9; p++) {
            float2 pv = upk2(acc[p]); v0[p] = pv.x; v1[p] = pv.y;
        }
        float bb0 = b_s[tx], bb1 = b_s[tx + 32];
        float* o0 = out + ((size_t)b * 64 + tx) * 108;
        float* o1 = out + ((size_t)b * 64 + tx + 32) * 108;
#pragma unroll
        for (int p = 0; p < 3; p++) {
            int po = grp * 3 + p;
            o0[po] = fmaxf(fmaxf(fmaxf(v0[3 * p], v0[3 * p + 1]), v0[3 * p + 2]) + bb0, 0.f);
            o1[po] = fmaxf(fmaxf(fmaxf(v1[3 * p], v1[3 * p + 1]), v1[3 * p + 2]) + bb1, 0.f);
        }
    }
#undef C2_LDG
#undef C2_STS
}

// ------------------------ conv3: 3xTF32 implicit GEMM ------------------------
// D[128 oc][104 pos] = K3[128][512] . B, B[r][n] = x[r/8][n + r%8]
// smem: xh[64*112] | xl[64*112] | wh[128*33] | wl[128*33]
#define C3M_XL  7168
#define C3M_WH  14336
#define C3M_WL  (14336 + 4224)
#define CONV3M_SMEM ((14336 + 2 * 4224) * 4)
__global__ void __launch_bounds__(256, 2) conv3_mma(
        const float* __restrict__ c2, const float* __restrict__ K3,
        const float* __restrict__ cb3, float* __restrict__ c3) {
    extern __shared__ __align__(16) float sm[];
    float* xh = sm;
    float* xl = sm + C3M_XL;
    float* wh = sm + C3M_WH;
    float* wl = sm + C3M_WL;
    int b = blockIdx.x;
    int tid = threadIdx.x;
    int lane = tid & 31, w = tid >> 5;
    int wm = w >> 1, wn = w & 1;           // 4 m-groups x 2 n-halves
    int g = lane >> 2, tg = lane & 3;

    // stage x (hi/lo tf32 split), rows padded to 112 with zeros
    for (int i = tid; i < 7168; i += 256) {
        int ic = i / 112, l = i % 112;
        float v = (l < 108) ? c2[(size_t)b * 6912 + ic * 108 + l] : 0.f;
        float h = tf32_hi(v);
        xh[i] = h;
        xl[i] = tf32_hi(v - h);
    }

    float acc[2][7][4] = {};
    for (int s = 0; s < 16; s++) {
        __syncthreads();
        // stage weight chunk [128 oc][32 r] (r = s*32 .. s*32+31), hi/lo split
        for (int i = tid; i < 4096; i += 256) {
            int oc = i >> 5, rr = i & 31;
            float v = K3[(size_t)oc * 512 + s * 32 + rr];
            float h = tf32_hi(v);
            wh[oc * 33 + rr] = h;
            wl[oc * 33 + rr] = tf32_hi(v - h);
        }
        __syncthreads();
#pragma unroll
        for (int ks = 0; ks < 4; ks++) {
            int ic = s * 4 + ks;               // r0 = s*32 + ks*8, ic = r0/8
            const float* xrh = xh + ic * 112;
            const float* xrl = xl + ic * 112;
            uint bh0[7], bh1[7], bl0[7], bl1[7];
#pragma unroll
            for (int nt = 0; nt < 7; nt++) {
                int ai = (wn * 7 + nt) * 8 + g + tg;   // n + k' (b0: k'=tg)
                bh0[nt] = __float_as_uint(xrh[ai]);
                bh1[nt] = __float_as_uint(xrh[ai + 4]);
                bl0[nt] = __float_as_uint(xrl[ai]);
                bl1[nt] = __float_as_uint(xrl[ai + 4]);
            }
#pragma unroll
            for (int mt = 0; mt < 2; mt++) {
                int ocr = wm * 32 + mt * 16 + g;
                int col = ks * 8 + tg;
                uint ah0 = __float_as_uint(wh[ocr * 33 + col]);
                uint ah1 = __float_as_uint(wh[(ocr + 8) * 33 + col]);
                uint ah2 = __float_as_uint(wh[ocr * 33 + col + 4]);
                uint ah3 = __float_as_uint(wh[(ocr + 8) * 33 + col + 4]);
                uint al0 = __float_as_uint(wl[ocr * 33 + col]);
                uint al1 = __float_as_uint(wl[(ocr + 8) * 33 + col]);
                uint al2 = __float_as_uint(wl[ocr * 33 + col + 4]);
                uint al3 = __float_as_uint(wl[(ocr + 8) * 33 + col + 4]);
#pragma unroll
                for (int nt = 0; nt < 7; nt++) {
                    mma_tf32(acc[mt][nt], al0, al1, al2, al3, bh0[nt], bh1[nt]);
                    mma_tf32(acc[mt][nt], ah0, ah1, ah2, ah3, bl0[nt], bl1[nt]);
                    mma_tf32(acc[mt][nt], ah0, ah1, ah2, ah3, bh0[nt], bh1[nt]);
                }
            }
        }
    }
    __syncthreads();
    // dump D to smem [128][112] (reuses xh+xl region = 14336 floats)
    float* dump = sm;
#pragma unroll
    for (int mt = 0; mt < 2; mt++) {
        int ocr = wm * 32 + mt * 16 + g;
#pragma unroll
        for (int nt = 0; nt < 7; nt++) {
            int n0 = (wn * 7 + nt) * 8 + 2 * tg;
            dump[ocr * 112 + n0]           = acc[mt][nt][0];
            dump[ocr * 112 + n0 + 1]       = acc[mt][nt][1];
            dump[(ocr + 8) * 112 + n0]     = acc[mt][nt][2];
            dump[(ocr + 8) * 112 + n0 + 1] = acc[mt][nt][3];
        }
    }
    __syncthreads();
    if (tid < 128) {
        float bb = cb3[tid];
        const float* row = dump + tid * 112;
        float ssum = 0.f;
#pragma unroll
        for (int gp = 0; gp < 33; gp++) {
            float v = fmaxf(fmaxf(row[3 * gp], row[3 * gp + 1]), row[3 * gp + 2]) + bb;
            ssum += fmaxf(v, 0.f);
        }
        c3[(size_t)b * 128 + tid] = ssum * (1.0f / 33.0f);
    }
}

// ------------------------ stream fork/join context --------------------------
struct Ctx {
    cudaStream_t s2 = nullptr;
    cudaEvent_t eF = nullptr, eJ = nullptr;
    bool ok = false;
    Ctx() {
        ok = (cudaStreamCreateWithFlags(&s2, cudaStreamNonBlocking) == cudaSuccess) &&
             (cudaEventCreateWithFlags(&eF, cudaEventDisableTiming) == cudaSuccess) &&
             (cudaEventCreateWithFlags(&eJ, cudaEventDisableTiming) == cudaSuccess);
    }
};
static Ctx g_ctx;

// ------------------------ host orchestration --------------------------------
extern "C" void kernel_launch(void* const* d_in, const int* in_sizes, int n_in,
                              void* d_out, int out_size) {
    const float* x    = (const float*)d_in[0];
    const int*   ei   = (const int*)d_in[1];
    const int*   batch= (const int*)d_in[2];
    const float* tgt  = (const float*)d_in[3];
    const float* W1 = (const float*)d_in[4];   const float* b1 = (const float*)d_in[5];
    const float* W2 = (const float*)d_in[6];   const float* b2 = (const float*)d_in[7];
    const float* W3 = (const float*)d_in[8];   const float* b3 = (const float*)d_in[9];
    const float* Wg1= (const float*)d_in[10];  const float* bg1= (const float*)d_in[11];
    const float* Wg2= (const float*)d_in[12];  const float* bg2= (const float*)d_in[13];
    const float* K1 = (const float*)d_in[14];  const float* cb1= (const float*)d_in[15];
    const float* K2 = (const float*)d_in[16];  const float* cb2= (const float*)d_in[17];
    const float* K3 = (const float*)d_in[18];  const float* cb3= (const float*)d_in[19];
    const float* Wxt= (const float*)d_in[20];  const float* bxt= (const float*)d_in[21];
    const float* Wf1= (const float*)d_in[22];  const float* bf1= (const float*)d_in[23];
    const float* Wf2= (const float*)d_in[24];  const float* bf2= (const float*)d_in[25];
    const float* Wo = (const float*)d_in[26];  const float* bo = (const float*)d_in[27];
    float* out = (float*)d_out;

    float *p_dis, *p_h, *p_feat, *p_agg, *p_pool, *p_t1, *p_xc, *p_c1, *p_c2, *p_c3, *p_f1, *p_f2;
    int* p_deg;
    cudaGetSymbolAddress((void**)&p_dis, g_dis);
    cudaGetSymbolAddress((void**)&p_deg, g_deg);
    cudaGetSymbolAddress((void**)&p_h, g_h);
    cudaGetSymbolAddress((void**)&p_feat, g_feat);
    cudaGetSymbolAddress((void**)&p_agg, g_agg);
    cudaGetSymbolAddress((void**)&p_pool, g_pool);
    cudaGetSymbolAddress((void**)&p_t1, g_t1);
    cudaGetSymbolAddress((void**)&p_xc, g_xc);
    cudaGetSymbolAddress((void**)&p_c1, g_c1);
    cudaGetSymbolAddress((void**)&p_c2, g_c2);
    cudaGetSymbolAddress((void**)&p_c3, g_c3);
    cudaGetSymbolAddress((void**)&p_f1, g_f1);
    cudaGetSymbolAddress((void**)&p_f2, g_f2);

    const int TPB = 256;
    const int gE = (EE + TPB - 1) / TPB;
    const int gN = (NN + TPB - 1) / TPB;

    bool fork = g_ctx.ok;
    cudaStream_t sg = fork ? g_ctx.s2 : (cudaStream_t)0;

    if (fork) {
        cudaEventRecord(g_ctx.eF, 0);
        cudaStreamWaitEvent(sg, g_ctx.eF, 0);
    }

    cudaFuncSetAttribute(conv2_kernel, cudaFuncAttributeMaxDynamicSharedMemorySize, CONV2_SMEM);
    cudaFuncSetAttribute(conv3_mma, cudaFuncAttributeMaxDynamicSharedMemorySize, CONV3M_SMEM);

    // Submission order: conv3_mma is the 6th launch (ncu -s 5 -c 1 window).
    cudaMemsetAsync(p_deg, 0, NN * sizeof(int), sg);                                 // 1
    deg_kernel<<<gE, TPB, 0, sg>>>(ei, p_deg);                                       // 2
    conv1_kernel<<<dim3(BB, 14), dim3(32, 8)>>>(tgt, K1, cb1, p_c1);                 // 3
    conv2_kernel<<<dim3(BB, 5), dim3(32, 8), CONV2_SMEM>>>(p_c1, K2, cb2, p_c2);     // 4
    cudaMemsetAsync(p_c3, 0, BB * 128 * sizeof(float));                              // 5
    conv3_mma<<<BB, 256, CONV3M_SMEM>>>(p_c2, K3, cb3, p_c3);                        // 6 <- profiled
    gemm_kernel<<<dim3(2, 8), 256>>>(p_c3, Wxt, bxt, p_xc, BB, 128, 128, 256, 128, 1);

    // ---- graph branch (stream sg) ----
    dis_kernel<<<gN, TPB, 0, sg>>>(p_deg, p_dis);
    transform1<<<gN, TPB, 0, sg>>>(x, W1, p_dis, p_h);
    cudaMemsetAsync(p_agg, 0, (size_t)NN * 4 * sizeof(float), sg);
    scatter_kernel<4><<<gE, TPB, 0, sg>>>(ei, p_h, p_agg);
    combine_transform<4, 8><<<gN, TPB, 0, sg>>>(p_agg, p_h, p_dis, b1, W2, p_feat);

    cudaMemsetAsync(p_agg, 0, (size_t)NN * 8 * sizeof(float), sg);
    scatter_kernel<8><<<gE, TPB, 0, sg>>>(ei, p_feat, p_agg);
    combine_transform<8, 16><<<gN, TPB, 0, sg>>>(p_agg, p_feat, p_dis, b2, W3, p_h);

    cudaMemsetAsync(p_agg, 0, (size_t)NN * 16 * sizeof(float), sg);
    scatter_kernel<16><<<gE, TPB, 0, sg>>>(ei, p_h, p_agg);
    cudaMemsetAsync(p_pool, 0, BB * 16 * sizeof(float), sg);
    combine_pool<<<gN, TPB, 0, sg>>>(p_agg, p_h, p_dis, b3, batch, p_pool);

    gemm_kernel<<<dim3(16, 8), 256, 0, sg>>>(p_pool, Wg1, bg1, p_t1, BB, 16, 1024, 1024, 0, 1);
    gemm_kernel<<<dim3(2, 8), 256, 0, sg>>>(p_t1, Wg2, bg2, p_xc, BB, 1024, 128, 256, 0, 0);
    if (fork) cudaEventRecord(g_ctx.eJ, sg);

    // ---- join + fusion head (stream 0) ----
    if (fork) cudaStreamWaitEvent(0, g_ctx.eJ, 0);
    gemm_kernel<<<dim3(16, 8), 256>>>(p_xc, Wf1, bf1, p_f1, BB, 256, 1024, 1024, 0, 1);
    gemm_kernel<<<dim3(8, 8), 256>>>(p_f1, Wf2, bf2, p_f2, BB, 1024, 512, 512, 0, 1);
    gemm_kernel<<<dim3(1, 8), 256>>>(p_f2, Wo, bo, out, BB, 512, 2, 2, 0, 0);
}